// round 2
// baseline (speedup 1.0000x reference)
#include <cuda_runtime.h>
#include <math.h>

#define BSZ 4
#define SEQ 2048
#define DIM 2048
#define NH  16
#define NKV 4
#define HD  128
#define KVD 512
#define TOK (BSZ*SEQ)          // 8192
#define NBH (BSZ*NH)           // 64
#define REP (NH/NKV)           // 4

// -------- scratch (device globals; no allocation allowed) --------
__device__ float g_qp[(size_t)TOK*DIM];            // q proj, token-major   67MB
__device__ float g_kp[(size_t)TOK*KVD];            // k proj                16.8MB
__device__ float g_vp[(size_t)TOK*KVD];            // v proj                16.8MB
__device__ float g_qt[(size_t)BSZ*NH*SEQ*HD];      // q [b,h,s,d] normed+rope+gain*scale
__device__ float g_kt[(size_t)BSZ*NKV*SEQ*HD];     // k [b,kh,s,d] normed+rope
__device__ float g_vt[(size_t)BSZ*NKV*SEQ*HD];     // v [b,kh,s,d]
__device__ float g_sc[(size_t)NBH*SEQ*SEQ];        // scores/probs          1.07GB
__device__ float g_ao[(size_t)TOK*DIM];            // attn out [b,s,h*d]    67MB

// ================= generic C[M,N] = A[M,K] * B[N,K]^T, 64x64x16 tiles ==========
__global__ void gemm64(const float* __restrict__ A, const float* __restrict__ B,
                       float* __restrict__ C, int M, int N, int K) {
    __shared__ float As[16][64];
    __shared__ float Bs[16][64];
    const int tid = threadIdx.x;
    const int tx = tid & 15, ty = tid >> 4;
    const int m0 = blockIdx.y * 64, n0 = blockIdx.x * 64;
    const int lr = tid >> 2;            // 0..63
    const int lc = (tid & 3) << 2;      // 0,4,8,12

    float acc[4][4] = {};
    for (int kk = 0; kk < K; kk += 16) {
        float4 av = *(const float4*)&A[(size_t)(m0 + lr) * K + kk + lc];
        float4 bv = *(const float4*)&B[(size_t)(n0 + lr) * K + kk + lc];
        As[lc+0][lr] = av.x; As[lc+1][lr] = av.y; As[lc+2][lr] = av.z; As[lc+3][lr] = av.w;
        Bs[lc+0][lr] = bv.x; Bs[lc+1][lr] = bv.y; Bs[lc+2][lr] = bv.z; Bs[lc+3][lr] = bv.w;
        __syncthreads();
        #pragma unroll
        for (int k = 0; k < 16; k++) {
            float a[4], b[4];
            #pragma unroll
            for (int i = 0; i < 4; i++) a[i] = As[k][ty*4 + i];
            #pragma unroll
            for (int j = 0; j < 4; j++) b[j] = Bs[k][tx*4 + j];
            #pragma unroll
            for (int i = 0; i < 4; i++)
                #pragma unroll
                for (int j = 0; j < 4; j++)
                    acc[i][j] += a[i] * b[j];
        }
        __syncthreads();
    }
    #pragma unroll
    for (int i = 0; i < 4; i++)
        #pragma unroll
        for (int j = 0; j < 4; j++)
            C[(size_t)(m0 + ty*4 + i) * N + n0 + tx*4 + j] = acc[i][j];
}

// ================= RMSNorm + RoPE (+gain*softmax-scale for q) =================
// one warp per (b, h, s); reads token-major proj, writes [b,h,s,d]
__device__ __forceinline__ void norm_rope_warp(const float* __restrict__ src,
                                               float* __restrict__ dst,
                                               int s, float mult) {
    const int lane = threadIdx.x & 31;
    float4 xv = *(const float4*)&src[lane * 4];
    float nn[4] = {xv.x, xv.y, xv.z, xv.w};
    float ss = nn[0]*nn[0] + nn[1]*nn[1] + nn[2]*nn[2] + nn[3]*nn[3];
    #pragma unroll
    for (int o = 16; o > 0; o >>= 1) ss += __shfl_xor_sync(0xffffffffu, ss, o);
    const float rms = rsqrtf(ss * (1.0f/128.0f) + 1.1920929e-7f);
    #pragma unroll
    for (int j = 0; j < 4; j++) nn[j] *= rms;

    const bool lo = lane < 16;
    float out[4];
    #pragma unroll
    for (int j = 0; j < 4; j++) {
        float partner = __shfl_xor_sync(0xffffffffu, nn[j], 16);
        int d = lane * 4 + j;
        int fi = lo ? d : d - 64;
        float ang = (float)s * powf(10000.0f, -(float)fi * (1.0f/64.0f));
        float sv, cv;
        sincosf(ang, &sv, &cv);
        // lo: x1 = nn, x2 = partner  -> x1*c + x2*s
        // hi: x1 = partner, x2 = nn  -> -x1*s + x2*c
        out[j] = lo ? (nn[j]*cv + partner*sv) : (nn[j]*cv - partner*sv);
        out[j] *= mult;
    }
    *(float4*)&dst[lane * 4] = make_float4(out[0], out[1], out[2], out[3]);
}

__global__ void qnorm_kernel(const float* __restrict__ gain) {
    int wid = (blockIdx.x * blockDim.x + threadIdx.x) >> 5;   // 0..NBH*SEQ-1
    int s = wid % SEQ;
    int bh = wid / SEQ;
    int b = bh / NH, h = bh % NH;
    const float* src = g_qp + (size_t)(b*SEQ + s) * DIM + h*HD;
    float* dst = g_qt + (size_t)bh * SEQ * HD + (size_t)s * HD;
    norm_rope_warp(src, dst, s, gain[h] * 0.08838834764831845f);  // gain * 1/sqrt(128)
}

__global__ void knorm_kernel() {
    int wid = (blockIdx.x * blockDim.x + threadIdx.x) >> 5;   // 0..BSZ*NKV*SEQ-1
    int s = wid % SEQ;
    int bh = wid / SEQ;
    int b = bh / NKV, h = bh % NKV;
    const float* src = g_kp + (size_t)(b*SEQ + s) * KVD + h*HD;
    float* dst = g_kt + (size_t)bh * SEQ * HD + (size_t)s * HD;
    norm_rope_warp(src, dst, s, 1.0f);
}

__global__ void vtrans_kernel() {
    int idx = blockIdx.x * blockDim.x + threadIdx.x;     // over TOK*KVD
    int tok = idx / KVD, c = idx % KVD;
    int b = tok / SEQ, s = tok % SEQ;
    int h = c / HD, d = c % HD;
    g_vt[(((size_t)(b*NKV + h)) * SEQ + s) * HD + d] = g_vp[(size_t)idx];
}

// ================= scores = Q K^T (causal tiles only; scale folded in Q) ======
__global__ void scores_kernel() {
    const int bh = blockIdx.z;
    const int i0 = blockIdx.y * 64, j0 = blockIdx.x * 64;
    if (j0 > i0) return;                       // tile fully above diagonal
    const int b = bh / NH, h = bh % NH;
    const float* A = g_qt + (size_t)bh * SEQ * HD;
    const float* B = g_kt + (size_t)(b*NKV + h/REP) * SEQ * HD;
    float* C = g_sc + (size_t)bh * SEQ * SEQ;

    __shared__ float As[16][64];
    __shared__ float Bs[16][64];
    const int tid = threadIdx.x;
    const int tx = tid & 15, ty = tid >> 4;
    const int lr = tid >> 2;
    const int lc = (tid & 3) << 2;

    float acc[4][4] = {};
    for (int kk = 0; kk < HD; kk += 16) {
        float4 av = *(const float4*)&A[(size_t)(i0 + lr) * HD + kk + lc];
        float4 bv = *(const float4*)&B[(size_t)(j0 + lr) * HD + kk + lc];
        As[lc+0][lr] = av.x; As[lc+1][lr] = av.y; As[lc+2][lr] = av.z; As[lc+3][lr] = av.w;
        Bs[lc+0][lr] = bv.x; Bs[lc+1][lr] = bv.y; Bs[lc+2][lr] = bv.z; Bs[lc+3][lr] = bv.w;
        __syncthreads();
        #pragma unroll
        for (int k = 0; k < 16; k++) {
            float a[4], bb[4];
            #pragma unroll
            for (int i = 0; i < 4; i++) a[i] = As[k][ty*4 + i];
            #pragma unroll
            for (int j = 0; j < 4; j++) bb[j] = Bs[k][tx*4 + j];
            #pragma unroll
            for (int i = 0; i < 4; i++)
                #pragma unroll
                for (int j = 0; j < 4; j++)
                    acc[i][j] += a[i] * bb[j];
        }
        __syncthreads();
    }
    #pragma unroll
    for (int i = 0; i < 4; i++)
        #pragma unroll
        for (int j = 0; j < 4; j++)
            C[(size_t)(i0 + ty*4 + i) * SEQ + j0 + tx*4 + j] = acc[i][j];
}

// ================= causal row softmax (in place on g_sc) ======================
// one 128-thread block per row; reads j in [0,i], writes probs, zeros to next 64-boundary
__global__ void softmax_kernel() {
    const int row = blockIdx.x;                 // 0..NBH*SEQ-1
    const int i = row % SEQ;
    float* p = g_sc + (size_t)(row / SEQ) * SEQ * SEQ + (size_t)i * SEQ;
    const int n = i + 1;
    const int tid = threadIdx.x;

    float vals[16];
    int cnt = 0;
    float mx = -INFINITY;
    for (int j = tid; j < n; j += 128) { float v = p[j]; vals[cnt++] = v; mx = fmaxf(mx, v); }

    __shared__ float red[128];
    red[tid] = mx; __syncthreads();
    #pragma unroll
    for (int s = 64; s > 0; s >>= 1) { if (tid < s) red[tid] = fmaxf(red[tid], red[tid+s]); __syncthreads(); }
    mx = red[0]; __syncthreads();

    float sum = 0.f;
    for (int c = 0; c < cnt; c++) { vals[c] = expf(vals[c] - mx); sum += vals[c]; }
    red[tid] = sum; __syncthreads();
    #pragma unroll
    for (int s = 64; s > 0; s >>= 1) { if (tid < s) red[tid] += red[tid+s]; __syncthreads(); }
    const float inv = 1.0f / red[0];

    cnt = 0;
    for (int j = tid; j < n; j += 128) p[j] = vals[cnt++] * inv;
    const int nend = ((i >> 6) + 1) << 6;       // next multiple of 64
    for (int j = n + tid; j < nend; j += 128) p[j] = 0.0f;
}

// ================= Y = P V (causal K-range), writes [b,s,h*d] =================
__global__ void pv_kernel() {
    const int bh = blockIdx.z;
    const int i0 = blockIdx.y * 64;
    const int b = bh / NH, h = bh % NH;
    const float* P = g_sc + (size_t)bh * SEQ * SEQ;
    const float* V = g_vt + (size_t)(b*NKV + h/REP) * SEQ * HD;

    __shared__ float Ps[32][64];     // [k][m]
    __shared__ float Vs[32][128];    // [k][n]
    const int tid = threadIdx.x;
    const int tx = tid & 15, ty = tid >> 4;

    float acc[4][8] = {};
    const int kend = i0 + 64;
    for (int kk = 0; kk < kend; kk += 32) {
        #pragma unroll
        for (int it = 0; it < 2; it++) {
            int r = (tid >> 3) + it * 32;
            int c = (tid & 7) << 2;
            float4 pv = *(const float4*)&P[(size_t)(i0 + r) * SEQ + kk + c];
            Ps[c+0][r] = pv.x; Ps[c+1][r] = pv.y; Ps[c+2][r] = pv.z; Ps[c+3][r] = pv.w;
        }
        #pragma unroll
        for (int it = 0; it < 4; it++) {
            int r = (tid >> 5) + it * 8;
            int c = (tid & 31) << 2;
            *(float4*)&Vs[r][c] = *(const float4*)&V[(size_t)(kk + r) * HD + c];
        }
        __syncthreads();
        #pragma unroll
        for (int k = 0; k < 32; k++) {
            float a[4], bb[8];
            #pragma unroll
            for (int i = 0; i < 4; i++) a[i] = Ps[k][ty*4 + i];
            #pragma unroll
            for (int j = 0; j < 8; j++) bb[j] = Vs[k][tx*8 + j];
            #pragma unroll
            for (int i = 0; i < 4; i++)
                #pragma unroll
                for (int j = 0; j < 8; j++)
                    acc[i][j] += a[i] * bb[j];
        }
        __syncthreads();
    }
    #pragma unroll
    for (int i = 0; i < 4; i++) {
        int srow = i0 + ty*4 + i;
        float* o = g_ao + (size_t)(b*SEQ + srow) * DIM + h*HD + tx*8;
        #pragma unroll
        for (int j = 0; j < 8; j++) o[j] = acc[i][j];
    }
}

// ================================ launch ======================================
extern "C" void kernel_launch(void* const* d_in, const int* in_sizes, int n_in,
                              void* d_out, int out_size) {
    const float* x    = (const float*)d_in[0];
    const float* Wq   = (const float*)d_in[1];
    const float* Wk   = (const float*)d_in[2];
    const float* Wv   = (const float*)d_in[3];
    const float* Wo   = (const float*)d_in[4];
    const float* gain = (const float*)d_in[5];
    float* out = (float*)d_out;

    float *qp, *kp, *vp, *ao;
    cudaGetSymbolAddress((void**)&qp, g_qp);
    cudaGetSymbolAddress((void**)&kp, g_kp);
    cudaGetSymbolAddress((void**)&vp, g_vp);
    cudaGetSymbolAddress((void**)&ao, g_ao);

    // projections
    gemm64<<<dim3(DIM/64, TOK/64), 256>>>(x, Wq, qp, TOK, DIM, DIM);
    gemm64<<<dim3(KVD/64, TOK/64), 256>>>(x, Wk, kp, TOK, KVD, DIM);
    gemm64<<<dim3(KVD/64, TOK/64), 256>>>(x, Wv, vp, TOK, KVD, DIM);

    // norm + rope + layout
    qnorm_kernel<<<(NBH*SEQ*32)/256, 256>>>(gain);          // 16384 blocks
    knorm_kernel<<<(BSZ*NKV*SEQ*32)/256, 256>>>();          // 4096 blocks
    vtrans_kernel<<<(TOK*KVD)/256, 256>>>();

    // attention
    scores_kernel<<<dim3(SEQ/64, SEQ/64, NBH), 256>>>();
    softmax_kernel<<<NBH*SEQ, 128>>>();
    pv_kernel<<<dim3(1, SEQ/64, NBH), 256>>>();

    // output projection
    gemm64<<<dim3(DIM/64, TOK/64), 256>>>(ao, Wo, out, TOK, DIM, DIM);
}

// round 4
// speedup vs baseline: 1.5077x; 1.5077x over previous
#include <cuda_runtime.h>
#include <math.h>

#define BSZ 4
#define SEQ 2048
#define DIM 2048
#define NH  16
#define NKV 4
#define HD  128
#define KVD 512
#define TOK (BSZ*SEQ)          // 8192
#define NBH (BSZ*NH)           // 64
#define REP (NH/NKV)           // 4

// -------- scratch (device globals; no allocation allowed) --------
__device__ float g_qp[(size_t)TOK*DIM];            // q proj, token-major
__device__ float g_kp[(size_t)TOK*KVD];            // k proj
__device__ float g_vp[(size_t)TOK*KVD];            // v proj
__device__ float g_qt[(size_t)BSZ*NH*SEQ*HD];      // q [b,h,s,d] normed+rope+gain*scale
__device__ float g_kt[(size_t)BSZ*NKV*SEQ*HD];     // k [b,kh,s,d] normed+rope
__device__ float g_vt[(size_t)BSZ*NKV*HD*SEQ];     // V^T [b,kh,d,s]
__device__ float g_sc[(size_t)NBH*SEQ*SEQ];        // scores/probs  1.07GB
__device__ float g_ao[(size_t)TOK*DIM];            // attn out [b,s,h*d]

// ===================== tf32 helpers =====================
__device__ __forceinline__ unsigned f2tf(float x) {
    unsigned r; asm("cvt.rna.tf32.f32 %0, %1;" : "=r"(r) : "f"(x)); return r;
}

__device__ __forceinline__ void mma8(float* c, const unsigned* a, unsigned b0, unsigned b1) {
    asm volatile(
        "mma.sync.aligned.m16n8k8.row.col.f32.tf32.tf32.f32 "
        "{%0,%1,%2,%3}, {%4,%5,%6,%7}, {%8,%9}, {%0,%1,%2,%3};"
        : "+f"(c[0]), "+f"(c[1]), "+f"(c[2]), "+f"(c[3])
        : "r"(a[0]), "r"(a[1]), "r"(a[2]), "r"(a[3]), "r"(b0), "r"(b1));
}

#define LDSTRIDE 20   // 16 k + 4 pad: conflict-free frag reads, aligned float4 region

__device__ __forceinline__ void stage16(unsigned* Ah, unsigned* Al, unsigned* Bh, unsigned* Bl,
                                        int r, int c8,
                                        float4 ra0, float4 ra1, float4 rb0, float4 rb1) {
    float av[8] = {ra0.x, ra0.y, ra0.z, ra0.w, ra1.x, ra1.y, ra1.z, ra1.w};
    float bv[8] = {rb0.x, rb0.y, rb0.z, rb0.w, rb1.x, rb1.y, rb1.z, rb1.w};
    #pragma unroll
    for (int j = 0; j < 8; j++) {
        unsigned ha = f2tf(av[j]);
        Ah[r*LDSTRIDE + c8 + j] = ha;
        Al[r*LDSTRIDE + c8 + j] = f2tf(av[j] - __uint_as_float(ha));
        unsigned hb = f2tf(bv[j]);
        Bh[r*LDSTRIDE + c8 + j] = hb;
        Bl[r*LDSTRIDE + c8 + j] = f2tf(bv[j] - __uint_as_float(hb));
    }
}

// ======= 128x128 block GEMM body: C = A[128,K] * B[128,K]^T  (3xTF32) =======
// A,B,C pre-offset to block origin. 256 threads.
__device__ __forceinline__ void gemm128_body(
    const float* __restrict__ A, int lda,
    const float* __restrict__ B, int ldb,
    float* __restrict__ C, int ldc, int K)
{
    __shared__ unsigned Ah[128*LDSTRIDE], Al[128*LDSTRIDE];
    __shared__ unsigned Bh[128*LDSTRIDE], Bl[128*LDSTRIDE];

    const int tid  = threadIdx.x;
    const int lane = tid & 31;
    const int wid  = tid >> 5;
    const int wm   = wid >> 1;        // 0..3
    const int wn   = wid & 1;         // 0..1
    const int r    = tid >> 1;        // 0..127 (loader row)
    const int c8   = (tid & 1) * 8;   // 0 or 8 (loader k-offset)
    const int gID  = lane >> 2;       // group id
    const int tig  = lane & 3;        // thread in group

    float c[2][8][4];
    #pragma unroll
    for (int i = 0; i < 2; i++)
        #pragma unroll
        for (int j = 0; j < 8; j++)
            #pragma unroll
            for (int q = 0; q < 4; q++) c[i][j][q] = 0.f;

    // prologue: k-tile 0
    float4 ra0 = *(const float4*)&A[(size_t)r*lda + c8];
    float4 ra1 = *(const float4*)&A[(size_t)r*lda + c8 + 4];
    float4 rb0 = *(const float4*)&B[(size_t)r*ldb + c8];
    float4 rb1 = *(const float4*)&B[(size_t)r*ldb + c8 + 4];
    stage16(Ah, Al, Bh, Bl, r, c8, ra0, ra1, rb0, rb1);
    __syncthreads();

    for (int kt = 16; ; kt += 16) {
        const bool more = kt < K;
        if (more) {
            ra0 = *(const float4*)&A[(size_t)r*lda + kt + c8];
            ra1 = *(const float4*)&A[(size_t)r*lda + kt + c8 + 4];
            rb0 = *(const float4*)&B[(size_t)r*ldb + kt + c8];
            rb1 = *(const float4*)&B[(size_t)r*ldb + kt + c8 + 4];
        }
        #pragma unroll
        for (int kk = 0; kk < 16; kk += 8) {
            unsigned ah[2][4], al[2][4];
            #pragma unroll
            for (int mt = 0; mt < 2; mt++) {
                int row = wm*32 + mt*16 + gID;
                int col = kk + tig;
                ah[mt][0] = Ah[row*LDSTRIDE + col];
                ah[mt][1] = Ah[(row+8)*LDSTRIDE + col];
                ah[mt][2] = Ah[row*LDSTRIDE + col + 4];
                ah[mt][3] = Ah[(row+8)*LDSTRIDE + col + 4];
                al[mt][0] = Al[row*LDSTRIDE + col];
                al[mt][1] = Al[(row+8)*LDSTRIDE + col];
                al[mt][2] = Al[row*LDSTRIDE + col + 4];
                al[mt][3] = Al[(row+8)*LDSTRIDE + col + 4];
            }
            #pragma unroll
            for (int nt = 0; nt < 8; nt++) {
                int n = wn*64 + nt*8 + gID;
                int k = kk + tig;
                unsigned bh0 = Bh[n*LDSTRIDE + k], bh1 = Bh[n*LDSTRIDE + k + 4];
                unsigned bl0 = Bl[n*LDSTRIDE + k], bl1 = Bl[n*LDSTRIDE + k + 4];
                #pragma unroll
                for (int mt = 0; mt < 2; mt++) {
                    mma8(c[mt][nt], ah[mt], bh0, bh1);   // hi*hi
                    mma8(c[mt][nt], al[mt], bh0, bh1);   // lo*hi
                    mma8(c[mt][nt], ah[mt], bl0, bl1);   // hi*lo
                }
            }
        }
        if (!more) break;
        __syncthreads();
        stage16(Ah, Al, Bh, Bl, r, c8, ra0, ra1, rb0, rb1);
        __syncthreads();
    }

    // epilogue
    #pragma unroll
    for (int mt = 0; mt < 2; mt++) {
        int row = wm*32 + mt*16 + gID;
        #pragma unroll
        for (int nt = 0; nt < 8; nt++) {
            int col = wn*64 + nt*8 + tig*2;
            *(float2*)&C[(size_t)row*ldc + col]     = make_float2(c[mt][nt][0], c[mt][nt][1]);
            *(float2*)&C[(size_t)(row+8)*ldc + col] = make_float2(c[mt][nt][2], c[mt][nt][3]);
        }
    }
}

// ====================== GEMM wrapper kernels ======================
__global__ void __launch_bounds__(256, 2) k_gemm(const float* __restrict__ A,
                                                 const float* __restrict__ B,
                                                 float* __restrict__ C,
                                                 int lda, int ldb, int ldc, int K) {
    gemm128_body(A + (size_t)blockIdx.y*128*lda, lda,
                 B + (size_t)blockIdx.x*128*ldb, ldb,
                 C + (size_t)blockIdx.y*128*ldc + blockIdx.x*128, ldc, K);
}

__global__ void __launch_bounds__(256, 2) k_scores() {
    const int bh = blockIdx.z;
    const int i0 = blockIdx.y * 128, j0 = blockIdx.x * 128;
    if (j0 > i0) return;
    const int b = bh / NH, h = bh % NH;
    gemm128_body(g_qt + (size_t)bh*SEQ*HD + (size_t)i0*HD, HD,
                 g_kt + (size_t)(b*NKV + h/REP)*SEQ*HD + (size_t)j0*HD, HD,
                 g_sc + (size_t)bh*SEQ*SEQ + (size_t)i0*SEQ + j0, SEQ, HD);
}

__global__ void __launch_bounds__(256, 2) k_pv() {
    const int bh = blockIdx.z;
    const int i0 = blockIdx.y * 128;
    const int b = bh / NH, h = bh % NH;
    gemm128_body(g_sc + (size_t)bh*SEQ*SEQ + (size_t)i0*SEQ, SEQ,
                 g_vt + (size_t)(b*NKV + h/REP)*HD*SEQ, SEQ,
                 g_ao + (size_t)(b*SEQ + i0)*DIM + h*HD, DIM, i0 + 128);
}

// ================= RMSNorm + RoPE (+gain*softmax-scale for q) =================
__device__ __forceinline__ void norm_rope_warp(const float* __restrict__ src,
                                               float* __restrict__ dst,
                                               int s, float mult) {
    const int lane = threadIdx.x & 31;
    float4 xv = *(const float4*)&src[lane * 4];
    float nn[4] = {xv.x, xv.y, xv.z, xv.w};
    float ss = nn[0]*nn[0] + nn[1]*nn[1] + nn[2]*nn[2] + nn[3]*nn[3];
    #pragma unroll
    for (int o = 16; o > 0; o >>= 1) ss += __shfl_xor_sync(0xffffffffu, ss, o);
    const float rms = rsqrtf(ss * (1.0f/128.0f) + 1.1920929e-7f);
    #pragma unroll
    for (int j = 0; j < 4; j++) nn[j] *= rms;

    const bool lo = lane < 16;
    float out[4];
    #pragma unroll
    for (int j = 0; j < 4; j++) {
        float partner = __shfl_xor_sync(0xffffffffu, nn[j], 16);
        int d = lane * 4 + j;
        int fi = lo ? d : d - 64;
        float ang = (float)s * powf(10000.0f, -(float)fi * (1.0f/64.0f));
        float sv, cv;
        sincosf(ang, &sv, &cv);
        out[j] = lo ? (nn[j]*cv + partner*sv) : (nn[j]*cv - partner*sv);
        out[j] *= mult;
    }
    *(float4*)&dst[lane * 4] = make_float4(out[0], out[1], out[2], out[3]);
}

__global__ void qnorm_kernel(const float* __restrict__ gain) {
    int wid = (blockIdx.x * blockDim.x + threadIdx.x) >> 5;
    int s = wid % SEQ;
    int bh = wid / SEQ;
    int b = bh / NH, h = bh % NH;
    const float* src = g_qp + (size_t)(b*SEQ + s) * DIM + h*HD;
    float* dst = g_qt + (size_t)bh * SEQ * HD + (size_t)s * HD;
    norm_rope_warp(src, dst, s, gain[h] * 0.08838834764831845f);
}

__global__ void knorm_kernel() {
    int wid = (blockIdx.x * blockDim.x + threadIdx.x) >> 5;
    int s = wid % SEQ;
    int bh = wid / SEQ;
    int b = bh / NKV, h = bh % NKV;
    const float* src = g_kp + (size_t)(b*SEQ + s) * KVD + h*HD;
    float* dst = g_kt + (size_t)bh * SEQ * HD + (size_t)s * HD;
    norm_rope_warp(src, dst, s, 1.0f);
}

// ============ tiled transpose: g_vp [b,s,(h,d)] -> g_vt [b,h,d,s] ============
__global__ void vtrans_kernel() {
    __shared__ float t[32][33];
    const int b  = blockIdx.z;
    const int s0 = blockIdx.x * 32;
    const int c0 = blockIdx.y * 32;             // column in KVD (never straddles a head)
    const int tx = threadIdx.x, ty = threadIdx.y;
    #pragma unroll
    for (int i = 0; i < 4; i++) {
        int row = ty + i*8;
        t[row][tx] = g_vp[((size_t)b*SEQ + s0 + row)*KVD + c0 + tx];
    }
    __syncthreads();
    const int h = c0 >> 7;
    const int dbase = c0 & 127;
    #pragma unroll
    for (int i = 0; i < 4; i++) {
        int row = ty + i*8;
        g_vt[(((size_t)(b*NKV + h))*HD + dbase + row)*SEQ + s0 + tx] = t[tx][row];
    }
}

// ================= causal row softmax (zero-pad to 128-boundary) ==============
__global__ void softmax_kernel() {
    const int row = blockIdx.x;
    const int i = row % SEQ;
    float* p = g_sc + (size_t)(row / SEQ) * SEQ * SEQ + (size_t)i * SEQ;
    const int n = i + 1;
    const int tid = threadIdx.x;

    float vals[16];
    int cnt = 0;
    float mx = -INFINITY;
    for (int j = tid; j < n; j += 128) { float v = p[j]; vals[cnt++] = v; mx = fmaxf(mx, v); }

    __shared__ float red[128];
    red[tid] = mx; __syncthreads();
    #pragma unroll
    for (int s = 64; s > 0; s >>= 1) { if (tid < s) red[tid] = fmaxf(red[tid], red[tid+s]); __syncthreads(); }
    mx = red[0]; __syncthreads();

    float sum = 0.f;
    for (int c = 0; c < cnt; c++) { vals[c] = expf(vals[c] - mx); sum += vals[c]; }
    red[tid] = sum; __syncthreads();
    #pragma unroll
    for (int s = 64; s > 0; s >>= 1) { if (tid < s) red[tid] += red[tid+s]; __syncthreads(); }
    const float inv = 1.0f / red[0];

    cnt = 0;
    for (int j = tid; j < n; j += 128) p[j] = vals[cnt++] * inv;
    const int nend = ((i >> 7) + 1) << 7;       // next multiple of 128
    for (int j = n + tid; j < nend; j += 128) p[j] = 0.0f;
}

// ================================ launch ======================================
extern "C" void kernel_launch(void* const* d_in, const int* in_sizes, int n_in,
                              void* d_out, int out_size) {
    const float* x    = (const float*)d_in[0];
    const float* Wq   = (const float*)d_in[1];
    const float* Wk   = (const float*)d_in[2];
    const float* Wv   = (const float*)d_in[3];
    const float* Wo   = (const float*)d_in[4];
    const float* gain = (const float*)d_in[5];
    float* out = (float*)d_out;

    float *qp, *kp, *vp, *ao;
    cudaGetSymbolAddress((void**)&qp, g_qp);
    cudaGetSymbolAddress((void**)&kp, g_kp);
    cudaGetSymbolAddress((void**)&vp, g_vp);
    cudaGetSymbolAddress((void**)&ao, g_ao);

    // projections (tensor tf32x3): C[M,N] = A[M,K] * B[N,K]^T
    k_gemm<<<dim3(DIM/128, TOK/128), 256>>>(x, Wq, qp, DIM, DIM, DIM, DIM);
    k_gemm<<<dim3(KVD/128, TOK/128), 256>>>(x, Wk, kp, DIM, DIM, KVD, DIM);
    k_gemm<<<dim3(KVD/128, TOK/128), 256>>>(x, Wv, vp, DIM, DIM, KVD, DIM);

    // norm + rope + V transpose
    qnorm_kernel<<<(NBH*SEQ*32)/256, 256>>>(gain);
    knorm_kernel<<<(BSZ*NKV*SEQ*32)/256, 256>>>();
    vtrans_kernel<<<dim3(SEQ/32, KVD/32, BSZ), dim3(32, 8)>>>();

    // attention
    k_scores<<<dim3(SEQ/128, SEQ/128, NBH), 256>>>();
    softmax_kernel<<<NBH*SEQ, 128>>>();
    k_pv<<<dim3(1, SEQ/128, NBH), 256>>>();

    // output projection
    k_gemm<<<dim3(DIM/128, TOK/128), 256>>>(ao, Wo, out, DIM, DIM, DIM, DIM);
}

// round 5
// speedup vs baseline: 1.6769x; 1.1122x over previous
#include <cuda_runtime.h>
#include <math.h>

#define BSZ 4
#define SEQ 2048
#define DIM 2048
#define NH  16
#define NKV 4
#define HD  128
#define KVD 512
#define TOK (BSZ*SEQ)          // 8192
#define NBH (BSZ*NH)           // 64
#define REP (NH/NKV)           // 4

// -------- scratch (device globals; no allocation allowed) --------
// split tf32 hi/lo operand arrays (u32 bit patterns)
__device__ unsigned g_xh [(size_t)TOK*DIM],  g_xl [(size_t)TOK*DIM];
__device__ unsigned g_wqh[(size_t)DIM*DIM],  g_wql[(size_t)DIM*DIM];
__device__ unsigned g_wkh[(size_t)KVD*DIM],  g_wkl[(size_t)KVD*DIM];
__device__ unsigned g_wvh[(size_t)KVD*DIM],  g_wvl[(size_t)KVD*DIM];
__device__ unsigned g_woh[(size_t)DIM*DIM],  g_wol[(size_t)DIM*DIM];
__device__ unsigned g_qth[(size_t)BSZ*NH*SEQ*HD],  g_qtl[(size_t)BSZ*NH*SEQ*HD];
__device__ unsigned g_kth[(size_t)BSZ*NKV*SEQ*HD], g_ktl[(size_t)BSZ*NKV*SEQ*HD];
__device__ unsigned g_vth[(size_t)BSZ*NKV*HD*SEQ], g_vtl[(size_t)BSZ*NKV*HD*SEQ];
__device__ unsigned g_ph [(size_t)NBH*SEQ*SEQ],    g_pl [(size_t)NBH*SEQ*SEQ];   // probs split
__device__ unsigned g_aoh[(size_t)TOK*DIM],  g_aol[(size_t)TOK*DIM];
// plain float intermediates
__device__ float g_qp[(size_t)TOK*DIM];
__device__ float g_kp[(size_t)TOK*KVD];
__device__ float g_vp[(size_t)TOK*KVD];
__device__ float g_sc[(size_t)NBH*SEQ*SEQ];        // raw scores 1.07GB

// ===================== tf32 helpers =====================
__device__ __forceinline__ unsigned f2tf(float x) {
    unsigned r; asm("cvt.rna.tf32.f32 %0, %1;" : "=r"(r) : "f"(x)); return r;
}
__device__ __forceinline__ void split2(float x, unsigned& h, unsigned& l) {
    h = f2tf(x); l = f2tf(x - __uint_as_float(h));
}

__device__ __forceinline__ void mma8(float* c, const unsigned* a, unsigned b0, unsigned b1) {
    asm volatile(
        "mma.sync.aligned.m16n8k8.row.col.f32.tf32.tf32.f32 "
        "{%0,%1,%2,%3}, {%4,%5,%6,%7}, {%8,%9}, {%0,%1,%2,%3};"
        : "+f"(c[0]), "+f"(c[1]), "+f"(c[2]), "+f"(c[3])
        : "r"(a[0]), "r"(a[1]), "r"(a[2]), "r"(a[3]), "r"(b0), "r"(b1));
}

__device__ __forceinline__ void cpa16(unsigned saddr, const unsigned* g) {
    asm volatile("cp.async.cg.shared.global [%0], [%1], 16;" :: "r"(saddr), "l"(g) : "memory");
}

#define LDSTRIDE 20           // 16 k + 4 pad (u32)
#define SMTILE   (128*LDSTRIDE)   // 2560 u32 per operand array
#define SMBUF    (4*SMTILE)       // u32 per buffer (Ah,Al,Bh,Bl)
#define SMEM_BYTES (2*SMBUF*4)    // 81920

// ======= 128x128 block GEMM: C = A[128,K] * B[128,K]^T  (3xTF32, cp.async db) =======
template<bool SPLIT_OUT>
__device__ __forceinline__ void gemm_body(
    const unsigned* __restrict__ Ahg, const unsigned* __restrict__ Alg, int lda,
    const unsigned* __restrict__ Bhg, const unsigned* __restrict__ Blg, int ldb,
    float* __restrict__ C, unsigned* __restrict__ Ch, unsigned* __restrict__ Cl,
    int ldc, int K)
{
    extern __shared__ unsigned sm[];
    const int tid  = threadIdx.x;
    const int lane = tid & 31;
    const int wid  = tid >> 5;
    const int wm   = wid >> 1;        // 0..3
    const int wn   = wid & 1;         // 0..1
    const int gID  = lane >> 2;
    const int tig  = lane & 3;
    const int r0   = tid >> 2;        // 0..63
    const int r1   = r0 + 64;
    const int kq   = (tid & 3) << 2;  // 0,4,8,12
    const unsigned sbase = (unsigned)__cvta_generic_to_shared(sm);

    float c[2][8][4];
    #pragma unroll
    for (int i = 0; i < 2; i++)
        #pragma unroll
        for (int j = 0; j < 8; j++)
            #pragma unroll
            for (int q = 0; q < 4; q++) c[i][j][q] = 0.f;

    auto issue = [&](int buf, int kt) {
        unsigned s = sbase + (unsigned)buf * (SMBUF*4);
        cpa16(s + (r0*LDSTRIDE + kq)*4,            Ahg + (size_t)r0*lda + kt + kq);
        cpa16(s + (r1*LDSTRIDE + kq)*4,            Ahg + (size_t)r1*lda + kt + kq);
        cpa16(s + (SMTILE + r0*LDSTRIDE + kq)*4,   Alg + (size_t)r0*lda + kt + kq);
        cpa16(s + (SMTILE + r1*LDSTRIDE + kq)*4,   Alg + (size_t)r1*lda + kt + kq);
        cpa16(s + (2*SMTILE + r0*LDSTRIDE + kq)*4, Bhg + (size_t)r0*ldb + kt + kq);
        cpa16(s + (2*SMTILE + r1*LDSTRIDE + kq)*4, Bhg + (size_t)r1*ldb + kt + kq);
        cpa16(s + (3*SMTILE + r0*LDSTRIDE + kq)*4, Blg + (size_t)r0*ldb + kt + kq);
        cpa16(s + (3*SMTILE + r1*LDSTRIDE + kq)*4, Blg + (size_t)r1*ldb + kt + kq);
        asm volatile("cp.async.commit_group;" ::: "memory");
    };

    issue(0, 0);
    const int T = K >> 4;
    for (int t = 0; t < T; t++) {
        const bool more = (t + 1) < T;
        if (more) {
            issue((t+1)&1, (t+1)<<4);
            asm volatile("cp.async.wait_group 1;" ::: "memory");
        } else {
            asm volatile("cp.async.wait_group 0;" ::: "memory");
        }
        __syncthreads();

        const unsigned* Ahs = sm + (t&1)*SMBUF;
        const unsigned* Als = Ahs + SMTILE;
        const unsigned* Bhs = Ahs + 2*SMTILE;
        const unsigned* Bls = Ahs + 3*SMTILE;

        #pragma unroll
        for (int kk = 0; kk < 16; kk += 8) {
            unsigned ah[2][4], al[2][4];
            #pragma unroll
            for (int mt = 0; mt < 2; mt++) {
                int row = wm*32 + mt*16 + gID;
                int col = kk + tig;
                ah[mt][0] = Ahs[row*LDSTRIDE + col];
                ah[mt][1] = Ahs[(row+8)*LDSTRIDE + col];
                ah[mt][2] = Ahs[row*LDSTRIDE + col + 4];
                ah[mt][3] = Ahs[(row+8)*LDSTRIDE + col + 4];
                al[mt][0] = Als[row*LDSTRIDE + col];
                al[mt][1] = Als[(row+8)*LDSTRIDE + col];
                al[mt][2] = Als[row*LDSTRIDE + col + 4];
                al[mt][3] = Als[(row+8)*LDSTRIDE + col + 4];
            }
            #pragma unroll
            for (int nt = 0; nt < 8; nt++) {
                int n = wn*64 + nt*8 + gID;
                int k = kk + tig;
                unsigned bh0 = Bhs[n*LDSTRIDE + k], bh1 = Bhs[n*LDSTRIDE + k + 4];
                unsigned bl0 = Bls[n*LDSTRIDE + k], bl1 = Bls[n*LDSTRIDE + k + 4];
                #pragma unroll
                for (int mt = 0; mt < 2; mt++) {
                    mma8(c[mt][nt], ah[mt], bh0, bh1);   // hi*hi
                    mma8(c[mt][nt], al[mt], bh0, bh1);   // lo*hi
                    mma8(c[mt][nt], ah[mt], bl0, bl1);   // hi*lo
                }
            }
        }
        __syncthreads();
    }

    // epilogue
    #pragma unroll
    for (int mt = 0; mt < 2; mt++) {
        int row = wm*32 + mt*16 + gID;
        #pragma unroll
        for (int nt = 0; nt < 8; nt++) {
            int col = wn*64 + nt*8 + tig*2;
            if (SPLIT_OUT) {
                unsigned h0, l0, h1, l1, h2, l2, h3, l3;
                split2(c[mt][nt][0], h0, l0); split2(c[mt][nt][1], h1, l1);
                split2(c[mt][nt][2], h2, l2); split2(c[mt][nt][3], h3, l3);
                *(uint2*)&Ch[(size_t)row*ldc + col]     = make_uint2(h0, h1);
                *(uint2*)&Cl[(size_t)row*ldc + col]     = make_uint2(l0, l1);
                *(uint2*)&Ch[(size_t)(row+8)*ldc + col] = make_uint2(h2, h3);
                *(uint2*)&Cl[(size_t)(row+8)*ldc + col] = make_uint2(l2, l3);
            } else {
                *(float2*)&C[(size_t)row*ldc + col]     = make_float2(c[mt][nt][0], c[mt][nt][1]);
                *(float2*)&C[(size_t)(row+8)*ldc + col] = make_float2(c[mt][nt][2], c[mt][nt][3]);
            }
        }
    }
}

// ====================== GEMM wrapper kernels ======================
__global__ void __launch_bounds__(256, 2) k_gemm(
    const unsigned* __restrict__ Ah, const unsigned* __restrict__ Al,
    const unsigned* __restrict__ Bh, const unsigned* __restrict__ Bl,
    float* __restrict__ C, int lda, int ldb, int ldc, int K)
{
    gemm_body<false>(Ah + (size_t)blockIdx.y*128*lda, Al + (size_t)blockIdx.y*128*lda, lda,
                     Bh + (size_t)blockIdx.x*128*ldb, Bl + (size_t)blockIdx.x*128*ldb, ldb,
                     C + (size_t)blockIdx.y*128*ldc + blockIdx.x*128, nullptr, nullptr,
                     ldc, K);
}

__global__ void __launch_bounds__(256, 2) k_scores() {
    const int bh = blockIdx.z;
    const int i0 = blockIdx.y * 128, j0 = blockIdx.x * 128;
    if (j0 > i0) return;
    const int b = bh / NH, h = bh % NH;
    const size_t qo = (size_t)bh*SEQ*HD + (size_t)i0*HD;
    const size_t ko = (size_t)(b*NKV + h/REP)*SEQ*HD + (size_t)j0*HD;
    gemm_body<false>(g_qth + qo, g_qtl + qo, HD,
                     g_kth + ko, g_ktl + ko, HD,
                     g_sc + (size_t)bh*SEQ*SEQ + (size_t)i0*SEQ + j0, nullptr, nullptr,
                     SEQ, HD);
}

__global__ void __launch_bounds__(256, 2) k_pv() {
    const int bh = blockIdx.z;
    const int i0 = blockIdx.y * 128;
    const int b = bh / NH, h = bh % NH;
    const size_t po = (size_t)bh*SEQ*SEQ + (size_t)i0*SEQ;
    const size_t vo = (size_t)(b*NKV + h/REP)*HD*SEQ;
    const size_t co = (size_t)(b*SEQ + i0)*DIM + h*HD;
    gemm_body<true>(g_ph + po, g_pl + po, SEQ,
                    g_vth + vo, g_vtl + vo, SEQ,
                    nullptr, g_aoh + co, g_aol + co, DIM, i0 + 128);
}

// ====================== pointwise split kernel ======================
__global__ void split_kernel(const float* __restrict__ src,
                             unsigned* __restrict__ hi, unsigned* __restrict__ lo) {
    size_t i = ((size_t)blockIdx.x * blockDim.x + threadIdx.x) * 4;
    float4 v = *(const float4*)&src[i];
    uint4 h, l;
    split2(v.x, h.x, l.x); split2(v.y, h.y, l.y);
    split2(v.z, h.z, l.z); split2(v.w, h.w, l.w);
    *(uint4*)&hi[i] = h; *(uint4*)&lo[i] = l;
}

// ================= RMSNorm + RoPE (+gain*softmax-scale for q), split output ====
__device__ __forceinline__ void norm_rope_warp(const float* __restrict__ src,
                                               unsigned* __restrict__ dsth,
                                               unsigned* __restrict__ dstl,
                                               int s, float mult) {
    const int lane = threadIdx.x & 31;
    float4 xv = *(const float4*)&src[lane * 4];
    float nn[4] = {xv.x, xv.y, xv.z, xv.w};
    float ss = nn[0]*nn[0] + nn[1]*nn[1] + nn[2]*nn[2] + nn[3]*nn[3];
    #pragma unroll
    for (int o = 16; o > 0; o >>= 1) ss += __shfl_xor_sync(0xffffffffu, ss, o);
    const float rms = rsqrtf(ss * (1.0f/128.0f) + 1.1920929e-7f);
    #pragma unroll
    for (int j = 0; j < 4; j++) nn[j] *= rms;

    const bool lo = lane < 16;
    uint4 oh, ol;
    unsigned* ohp = &oh.x; unsigned* olp = &ol.x;
    #pragma unroll
    for (int j = 0; j < 4; j++) {
        float partner = __shfl_xor_sync(0xffffffffu, nn[j], 16);
        int d = lane * 4 + j;
        int fi = lo ? d : d - 64;
        float ang = (float)s * powf(10000.0f, -(float)fi * (1.0f/64.0f));
        float sv, cv;
        sincosf(ang, &sv, &cv);
        float out = lo ? (nn[j]*cv + partner*sv) : (nn[j]*cv - partner*sv);
        out *= mult;
        split2(out, ohp[j], olp[j]);
    }
    *(uint4*)&dsth[lane * 4] = oh;
    *(uint4*)&dstl[lane * 4] = ol;
}

__global__ void qnorm_kernel(const float* __restrict__ gain) {
    int wid = (blockIdx.x * blockDim.x + threadIdx.x) >> 5;
    int s = wid % SEQ;
    int bh = wid / SEQ;
    int b = bh / NH, h = bh % NH;
    const float* src = g_qp + (size_t)(b*SEQ + s) * DIM + h*HD;
    size_t off = (size_t)bh * SEQ * HD + (size_t)s * HD;
    norm_rope_warp(src, g_qth + off, g_qtl + off, s, gain[h] * 0.08838834764831845f);
}

__global__ void knorm_kernel() {
    int wid = (blockIdx.x * blockDim.x + threadIdx.x) >> 5;
    int s = wid % SEQ;
    int bh = wid / SEQ;
    int b = bh / NKV, h = bh % NKV;
    const float* src = g_kp + (size_t)(b*SEQ + s) * KVD + h*HD;
    size_t off = (size_t)bh * SEQ * HD + (size_t)s * HD;
    norm_rope_warp(src, g_kth + off, g_ktl + off, s, 1.0f);
}

// ============ tiled transpose: g_vp [b,s,(h,d)] -> split V^T [b,h,d,s] ========
__global__ void vtrans_kernel() {
    __shared__ float t[32][33];
    const int b  = blockIdx.z;
    const int s0 = blockIdx.x * 32;
    const int c0 = blockIdx.y * 32;
    const int tx = threadIdx.x, ty = threadIdx.y;
    #pragma unroll
    for (int i = 0; i < 4; i++) {
        int row = ty + i*8;
        t[row][tx] = g_vp[((size_t)b*SEQ + s0 + row)*KVD + c0 + tx];
    }
    __syncthreads();
    const int h = c0 >> 7;
    const int dbase = c0 & 127;
    #pragma unroll
    for (int i = 0; i < 4; i++) {
        int row = ty + i*8;
        float v = t[tx][row];
        unsigned hh, ll; split2(v, hh, ll);
        size_t idx = (((size_t)(b*NKV + h))*HD + dbase + row)*SEQ + s0 + tx;
        g_vth[idx] = hh; g_vtl[idx] = ll;
    }
}

// ====== causal row softmax: reads g_sc, writes split probs (pad to 128) =======
__global__ void softmax_kernel() {
    const int row = blockIdx.x;
    const int i = row % SEQ;
    const size_t off = (size_t)(row / SEQ) * SEQ * SEQ + (size_t)i * SEQ;
    const float* p = g_sc + off;
    const int n = i + 1;
    const int tid = threadIdx.x;

    float vals[16];
    int cnt = 0;
    float mx = -INFINITY;
    for (int j = tid; j < n; j += 128) { float v = p[j]; vals[cnt++] = v; mx = fmaxf(mx, v); }

    __shared__ float red[128];
    red[tid] = mx; __syncthreads();
    #pragma unroll
    for (int s = 64; s > 0; s >>= 1) { if (tid < s) red[tid] = fmaxf(red[tid], red[tid+s]); __syncthreads(); }
    mx = red[0]; __syncthreads();

    float sum = 0.f;
    for (int c = 0; c < cnt; c++) { vals[c] = expf(vals[c] - mx); sum += vals[c]; }
    red[tid] = sum; __syncthreads();
    #pragma unroll
    for (int s = 64; s > 0; s >>= 1) { if (tid < s) red[tid] += red[tid+s]; __syncthreads(); }
    const float inv = 1.0f / red[0];

    cnt = 0;
    for (int j = tid; j < n; j += 128) {
        float pv = vals[cnt++] * inv;
        unsigned h, l; split2(pv, h, l);
        g_ph[off + j] = h; g_pl[off + j] = l;
    }
    const int nend = ((i >> 7) + 1) << 7;
    for (int j = n + tid; j < nend; j += 128) { g_ph[off + j] = 0u; g_pl[off + j] = 0u; }
}

// ================================ launch ======================================
extern "C" void kernel_launch(void* const* d_in, const int* in_sizes, int n_in,
                              void* d_out, int out_size) {
    const float* x    = (const float*)d_in[0];
    const float* Wq   = (const float*)d_in[1];
    const float* Wk   = (const float*)d_in[2];
    const float* Wv   = (const float*)d_in[3];
    const float* Wo   = (const float*)d_in[4];
    const float* gain = (const float*)d_in[5];
    float* out = (float*)d_out;

    static int attr_done = 0;
    if (!attr_done) {
        cudaFuncSetAttribute(k_gemm,   cudaFuncAttributeMaxDynamicSharedMemorySize, SMEM_BYTES);
        cudaFuncSetAttribute(k_scores, cudaFuncAttributeMaxDynamicSharedMemorySize, SMEM_BYTES);
        cudaFuncSetAttribute(k_pv,     cudaFuncAttributeMaxDynamicSharedMemorySize, SMEM_BYTES);
        attr_done = 1;
    }

    unsigned *xh, *xl, *wqh, *wql, *wkh, *wkl, *wvh, *wvl, *woh, *wol, *aoh, *aol;
    float *qp, *kp, *vp;
    cudaGetSymbolAddress((void**)&xh,  g_xh);  cudaGetSymbolAddress((void**)&xl,  g_xl);
    cudaGetSymbolAddress((void**)&wqh, g_wqh); cudaGetSymbolAddress((void**)&wql, g_wql);
    cudaGetSymbolAddress((void**)&wkh, g_wkh); cudaGetSymbolAddress((void**)&wkl, g_wkl);
    cudaGetSymbolAddress((void**)&wvh, g_wvh); cudaGetSymbolAddress((void**)&wvl, g_wvl);
    cudaGetSymbolAddress((void**)&woh, g_woh); cudaGetSymbolAddress((void**)&wol, g_wol);
    cudaGetSymbolAddress((void**)&aoh, g_aoh); cudaGetSymbolAddress((void**)&aol, g_aol);
    cudaGetSymbolAddress((void**)&qp,  g_qp);
    cudaGetSymbolAddress((void**)&kp,  g_kp);
    cudaGetSymbolAddress((void**)&vp,  g_vp);

    // 0-4: operand splits (tf32 hi/lo)
    split_kernel<<<(TOK*DIM)/1024, 256>>>(x,  xh,  xl);
    split_kernel<<<(DIM*DIM)/1024, 256>>>(Wq, wqh, wql);
    split_kernel<<<(KVD*DIM)/1024, 256>>>(Wk, wkh, wkl);
    split_kernel<<<(KVD*DIM)/1024, 256>>>(Wv, wvh, wvl);
    split_kernel<<<(DIM*DIM)/1024, 256>>>(Wo, woh, wol);

    // 5-7: projections (launch 5 = Q proj → ncu target)
    k_gemm<<<dim3(DIM/128, TOK/128), 256, SMEM_BYTES>>>(xh, xl, wqh, wql, qp, DIM, DIM, DIM, DIM);
    k_gemm<<<dim3(KVD/128, TOK/128), 256, SMEM_BYTES>>>(xh, xl, wkh, wkl, kp, DIM, DIM, KVD, DIM);
    k_gemm<<<dim3(KVD/128, TOK/128), 256, SMEM_BYTES>>>(xh, xl, wvh, wvl, vp, DIM, DIM, KVD, DIM);

    // norm + rope + V transpose (split outputs)
    qnorm_kernel<<<(NBH*SEQ*32)/256, 256>>>(gain);
    knorm_kernel<<<(BSZ*NKV*SEQ*32)/256, 256>>>();
    vtrans_kernel<<<dim3(SEQ/32, KVD/32, BSZ), dim3(32, 8)>>>();

    // attention
    k_scores<<<dim3(SEQ/128, SEQ/128, NBH), 256, SMEM_BYTES>>>();
    softmax_kernel<<<NBH*SEQ, 128>>>();
    k_pv<<<dim3(1, SEQ/128, NBH), 256, SMEM_BYTES>>>();

    // output projection
    k_gemm<<<dim3(DIM/128, TOK/128), 256, SMEM_BYTES>>>(aoh, aol, woh, wol, out, DIM, DIM, DIM, DIM);
}

// round 6
// speedup vs baseline: 2.3099x; 1.3775x over previous
#include <cuda_runtime.h>
#include <math.h>

#define BSZ 4
#define SEQ 2048
#define DIM 2048
#define NH  16
#define NKV 4
#define HD  128
#define KVD 512
#define TOK (BSZ*SEQ)          // 8192
#define NBH (BSZ*NH)           // 64
#define REP (NH/NKV)           // 4

// -------- scratch (device globals; no allocation allowed) --------
// tf32 operand arrays (u32 bit patterns). A-side: hi+lo. B-side: hi only.
__device__ unsigned g_xh [(size_t)TOK*DIM],  g_xl [(size_t)TOK*DIM];
__device__ unsigned g_wqh[(size_t)DIM*DIM];
__device__ unsigned g_wkh[(size_t)KVD*DIM];
__device__ unsigned g_wvh[(size_t)KVD*DIM];
__device__ unsigned g_woh[(size_t)DIM*DIM];
__device__ unsigned g_qth[(size_t)BSZ*NH*SEQ*HD],  g_qtl[(size_t)BSZ*NH*SEQ*HD];
__device__ unsigned g_kth[(size_t)BSZ*NKV*SEQ*HD];
__device__ unsigned g_vth[(size_t)BSZ*NKV*HD*SEQ];
__device__ unsigned g_ph [(size_t)NBH*SEQ*SEQ],    g_pl [(size_t)NBH*SEQ*SEQ];
__device__ unsigned g_aoh[(size_t)TOK*DIM],  g_aol[(size_t)TOK*DIM];
// plain float intermediates
__device__ float g_qp[(size_t)TOK*DIM];
__device__ float g_kp[(size_t)TOK*KVD];
__device__ float g_vp[(size_t)TOK*KVD];
__device__ float g_sc[(size_t)NBH*SEQ*SEQ];        // raw scores 1.07GB

// ===================== tf32 helpers =====================
__device__ __forceinline__ unsigned f2tf(float x) {
    unsigned r; asm("cvt.rna.tf32.f32 %0, %1;" : "=r"(r) : "f"(x)); return r;
}
__device__ __forceinline__ void split2(float x, unsigned& h, unsigned& l) {
    h = f2tf(x); l = f2tf(x - __uint_as_float(h));
}

__device__ __forceinline__ void mma8(float* c, const unsigned* a, unsigned b0, unsigned b1) {
    asm volatile(
        "mma.sync.aligned.m16n8k8.row.col.f32.tf32.tf32.f32 "
        "{%0,%1,%2,%3}, {%4,%5,%6,%7}, {%8,%9}, {%0,%1,%2,%3};"
        : "+f"(c[0]), "+f"(c[1]), "+f"(c[2]), "+f"(c[3])
        : "r"(a[0]), "r"(a[1]), "r"(a[2]), "r"(a[3]), "r"(b0), "r"(b1));
}

__device__ __forceinline__ void cpa16(unsigned saddr, const unsigned* g) {
    asm volatile("cp.async.cg.shared.global [%0], [%1], 16;" :: "r"(saddr), "l"(g) : "memory");
}

#define LDSTRIDE 20               // 16 k + 4 pad (u32)
#define SMTILE   (128*LDSTRIDE)   // 2560 u32 per operand array
#define SMBUF    (3*SMTILE)       // u32 per buffer (Ah,Al,Bh)
#define SMEM_BYTES (2*SMBUF*4)    // 61440

// ======= 128x128 block GEMM: C = A[128,K] * B[128,K]^T  (2-term tf32 split) ====
// terms: A_hi*B_hi + A_lo*B_hi
template<bool SPLIT_OUT>
__device__ __forceinline__ void gemm_body(
    const unsigned* __restrict__ Ahg, const unsigned* __restrict__ Alg, int lda,
    const unsigned* __restrict__ Bhg, int ldb,
    float* __restrict__ C, unsigned* __restrict__ Ch, unsigned* __restrict__ Cl,
    int ldc, int K)
{
    extern __shared__ unsigned sm[];
    const int tid  = threadIdx.x;
    const int lane = tid & 31;
    const int wid  = tid >> 5;
    const int wm   = wid >> 1;        // 0..3
    const int wn   = wid & 1;         // 0..1
    const int gID  = lane >> 2;
    const int tig  = lane & 3;
    const int r0   = tid >> 2;        // 0..63
    const int r1   = r0 + 64;
    const int kq   = (tid & 3) << 2;  // 0,4,8,12
    const unsigned sbase = (unsigned)__cvta_generic_to_shared(sm);

    float c[2][8][4];
    #pragma unroll
    for (int i = 0; i < 2; i++)
        #pragma unroll
        for (int j = 0; j < 8; j++)
            #pragma unroll
            for (int q = 0; q < 4; q++) c[i][j][q] = 0.f;

    auto issue = [&](int buf, int kt) {
        unsigned s = sbase + (unsigned)buf * (SMBUF*4);
        cpa16(s + (r0*LDSTRIDE + kq)*4,            Ahg + (size_t)r0*lda + kt + kq);
        cpa16(s + (r1*LDSTRIDE + kq)*4,            Ahg + (size_t)r1*lda + kt + kq);
        cpa16(s + (SMTILE + r0*LDSTRIDE + kq)*4,   Alg + (size_t)r0*lda + kt + kq);
        cpa16(s + (SMTILE + r1*LDSTRIDE + kq)*4,   Alg + (size_t)r1*lda + kt + kq);
        cpa16(s + (2*SMTILE + r0*LDSTRIDE + kq)*4, Bhg + (size_t)r0*ldb + kt + kq);
        cpa16(s + (2*SMTILE + r1*LDSTRIDE + kq)*4, Bhg + (size_t)r1*ldb + kt + kq);
        asm volatile("cp.async.commit_group;" ::: "memory");
    };

    issue(0, 0);
    const int T = K >> 4;
    for (int t = 0; t < T; t++) {
        const bool more = (t + 1) < T;
        if (more) {
            issue((t+1)&1, (t+1)<<4);
            asm volatile("cp.async.wait_group 1;" ::: "memory");
        } else {
            asm volatile("cp.async.wait_group 0;" ::: "memory");
        }
        __syncthreads();

        const unsigned* Ahs = sm + (t&1)*SMBUF;
        const unsigned* Als = Ahs + SMTILE;
        const unsigned* Bhs = Ahs + 2*SMTILE;

        #pragma unroll
        for (int kk = 0; kk < 16; kk += 8) {
            unsigned ah[2][4], al[2][4];
            #pragma unroll
            for (int mt = 0; mt < 2; mt++) {
                int row = wm*32 + mt*16 + gID;
                int col = kk + tig;
                ah[mt][0] = Ahs[row*LDSTRIDE + col];
                ah[mt][1] = Ahs[(row+8)*LDSTRIDE + col];
                ah[mt][2] = Ahs[row*LDSTRIDE + col + 4];
                ah[mt][3] = Ahs[(row+8)*LDSTRIDE + col + 4];
                al[mt][0] = Als[row*LDSTRIDE + col];
                al[mt][1] = Als[(row+8)*LDSTRIDE + col];
                al[mt][2] = Als[row*LDSTRIDE + col + 4];
                al[mt][3] = Als[(row+8)*LDSTRIDE + col + 4];
            }
            #pragma unroll
            for (int nt = 0; nt < 8; nt++) {
                int n = wn*64 + nt*8 + gID;
                int k = kk + tig;
                unsigned bh0 = Bhs[n*LDSTRIDE + k], bh1 = Bhs[n*LDSTRIDE + k + 4];
                #pragma unroll
                for (int mt = 0; mt < 2; mt++) {
                    mma8(c[mt][nt], ah[mt], bh0, bh1);   // hi*hi
                    mma8(c[mt][nt], al[mt], bh0, bh1);   // lo*hi
                }
            }
        }
        __syncthreads();
    }

    // epilogue
    #pragma unroll
    for (int mt = 0; mt < 2; mt++) {
        int row = wm*32 + mt*16 + gID;
        #pragma unroll
        for (int nt = 0; nt < 8; nt++) {
            int col = wn*64 + nt*8 + tig*2;
            if (SPLIT_OUT) {
                unsigned h0, l0, h1, l1, h2, l2, h3, l3;
                split2(c[mt][nt][0], h0, l0); split2(c[mt][nt][1], h1, l1);
                split2(c[mt][nt][2], h2, l2); split2(c[mt][nt][3], h3, l3);
                *(uint2*)&Ch[(size_t)row*ldc + col]     = make_uint2(h0, h1);
                *(uint2*)&Cl[(size_t)row*ldc + col]     = make_uint2(l0, l1);
                *(uint2*)&Ch[(size_t)(row+8)*ldc + col] = make_uint2(h2, h3);
                *(uint2*)&Cl[(size_t)(row+8)*ldc + col] = make_uint2(l2, l3);
            } else {
                *(float2*)&C[(size_t)row*ldc + col]     = make_float2(c[mt][nt][0], c[mt][nt][1]);
                *(float2*)&C[(size_t)(row+8)*ldc + col] = make_float2(c[mt][nt][2], c[mt][nt][3]);
            }
        }
    }
}

// ====================== GEMM wrapper kernels ======================
__global__ void __launch_bounds__(256, 2) k_gemm(
    const unsigned* __restrict__ Ah, const unsigned* __restrict__ Al,
    const unsigned* __restrict__ Bh,
    float* __restrict__ C, int lda, int ldb, int ldc, int K)
{
    gemm_body<false>(Ah + (size_t)blockIdx.y*128*lda, Al + (size_t)blockIdx.y*128*lda, lda,
                     Bh + (size_t)blockIdx.x*128*ldb, ldb,
                     C + (size_t)blockIdx.y*128*ldc + blockIdx.x*128, nullptr, nullptr,
                     ldc, K);
}

__global__ void __launch_bounds__(256, 2) k_scores() {
    const int bh = blockIdx.z;
    const int i0 = blockIdx.y * 128, j0 = blockIdx.x * 128;
    if (j0 > i0) return;
    const int b = bh / NH, h = bh % NH;
    const size_t qo = (size_t)bh*SEQ*HD + (size_t)i0*HD;
    const size_t ko = (size_t)(b*NKV + h/REP)*SEQ*HD + (size_t)j0*HD;
    gemm_body<false>(g_qth + qo, g_qtl + qo, HD,
                     g_kth + ko, HD,
                     g_sc + (size_t)bh*SEQ*SEQ + (size_t)i0*SEQ + j0, nullptr, nullptr,
                     SEQ, HD);
}

__global__ void __launch_bounds__(256, 2) k_pv() {
    const int bh = blockIdx.z;
    const int i0 = blockIdx.y * 128;
    const int b = bh / NH, h = bh % NH;
    const size_t po = (size_t)bh*SEQ*SEQ + (size_t)i0*SEQ;
    const size_t vo = (size_t)(b*NKV + h/REP)*HD*SEQ;
    const size_t co = (size_t)(b*SEQ + i0)*DIM + h*HD;
    gemm_body<true>(g_ph + po, g_pl + po, SEQ,
                    g_vth + vo, SEQ,
                    nullptr, g_aoh + co, g_aol + co, DIM, i0 + 128);
}

// ====================== pointwise split kernels ======================
__global__ void split_kernel(const float* __restrict__ src,
                             unsigned* __restrict__ hi, unsigned* __restrict__ lo) {
    size_t i = ((size_t)blockIdx.x * blockDim.x + threadIdx.x) * 4;
    float4 v = *(const float4*)&src[i];
    uint4 h, l;
    split2(v.x, h.x, l.x); split2(v.y, h.y, l.y);
    split2(v.z, h.z, l.z); split2(v.w, h.w, l.w);
    *(uint4*)&hi[i] = h; *(uint4*)&lo[i] = l;
}

__global__ void splithi_kernel(const float* __restrict__ src, unsigned* __restrict__ hi) {
    size_t i = ((size_t)blockIdx.x * blockDim.x + threadIdx.x) * 4;
    float4 v = *(const float4*)&src[i];
    *(uint4*)&hi[i] = make_uint4(f2tf(v.x), f2tf(v.y), f2tf(v.z), f2tf(v.w));
}

// ================= RMSNorm + RoPE (+gain*softmax-scale for q) =================
template<bool WRITE_LO>
__device__ __forceinline__ void norm_rope_warp(const float* __restrict__ src,
                                               unsigned* __restrict__ dsth,
                                               unsigned* __restrict__ dstl,
                                               int s, float mult) {
    const int lane = threadIdx.x & 31;
    float4 xv = *(const float4*)&src[lane * 4];
    float nn[4] = {xv.x, xv.y, xv.z, xv.w};
    float ss = nn[0]*nn[0] + nn[1]*nn[1] + nn[2]*nn[2] + nn[3]*nn[3];
    #pragma unroll
    for (int o = 16; o > 0; o >>= 1) ss += __shfl_xor_sync(0xffffffffu, ss, o);
    const float rms = rsqrtf(ss * (1.0f/128.0f) + 1.1920929e-7f);
    #pragma unroll
    for (int j = 0; j < 4; j++) nn[j] *= rms;

    const bool lo = lane < 16;
    uint4 oh, ol;
    unsigned* ohp = &oh.x; unsigned* olp = &ol.x;
    #pragma unroll
    for (int j = 0; j < 4; j++) {
        float partner = __shfl_xor_sync(0xffffffffu, nn[j], 16);
        int d = lane * 4 + j;
        int fi = lo ? d : d - 64;
        float ang = (float)s * powf(10000.0f, -(float)fi * (1.0f/64.0f));
        float sv, cv;
        sincosf(ang, &sv, &cv);
        float out = lo ? (nn[j]*cv + partner*sv) : (nn[j]*cv - partner*sv);
        out *= mult;
        if (WRITE_LO) split2(out, ohp[j], olp[j]);
        else          ohp[j] = f2tf(out);
    }
    *(uint4*)&dsth[lane * 4] = oh;
    if (WRITE_LO) *(uint4*)&dstl[lane * 4] = ol;
}

__global__ void qnorm_kernel(const float* __restrict__ gain) {
    int wid = (blockIdx.x * blockDim.x + threadIdx.x) >> 5;
    int s = wid % SEQ;
    int bh = wid / SEQ;
    int b = bh / NH, h = bh % NH;
    const float* src = g_qp + (size_t)(b*SEQ + s) * DIM + h*HD;
    size_t off = (size_t)bh * SEQ * HD + (size_t)s * HD;
    norm_rope_warp<true>(src, g_qth + off, g_qtl + off, s, gain[h] * 0.08838834764831845f);
}

__global__ void knorm_kernel() {
    int wid = (blockIdx.x * blockDim.x + threadIdx.x) >> 5;
    int s = wid % SEQ;
    int bh = wid / SEQ;
    int b = bh / NKV, h = bh % NKV;
    const float* src = g_kp + (size_t)(b*SEQ + s) * KVD + h*HD;
    size_t off = (size_t)bh * SEQ * HD + (size_t)s * HD;
    norm_rope_warp<false>(src, g_kth + off, nullptr, s, 1.0f);
}

// ============ tiled transpose: g_vp [b,s,(h,d)] -> V^T hi [b,h,d,s] ==========
__global__ void vtrans_kernel() {
    __shared__ float t[32][33];
    const int b  = blockIdx.z;
    const int s0 = blockIdx.x * 32;
    const int c0 = blockIdx.y * 32;
    const int tx = threadIdx.x, ty = threadIdx.y;
    #pragma unroll
    for (int i = 0; i < 4; i++) {
        int row = ty + i*8;
        t[row][tx] = g_vp[((size_t)b*SEQ + s0 + row)*KVD + c0 + tx];
    }
    __syncthreads();
    const int h = c0 >> 7;
    const int dbase = c0 & 127;
    #pragma unroll
    for (int i = 0; i < 4; i++) {
        int row = ty + i*8;
        size_t idx = (((size_t)(b*NKV + h))*HD + dbase + row)*SEQ + s0 + tx;
        g_vth[idx] = f2tf(t[tx][row]);
    }
}

// ====== causal row softmax: reads g_sc, writes split probs (pad to 128) =======
__global__ void softmax_kernel() {
    const int row = blockIdx.x;
    const int i = row % SEQ;
    const size_t off = (size_t)(row / SEQ) * SEQ * SEQ + (size_t)i * SEQ;
    const float* p = g_sc + off;
    const int n = i + 1;
    const int tid = threadIdx.x;

    float vals[16];
    int cnt = 0;
    float mx = -INFINITY;
    for (int j = tid; j < n; j += 128) { float v = p[j]; vals[cnt++] = v; mx = fmaxf(mx, v); }

    __shared__ float red[128];
    red[tid] = mx; __syncthreads();
    #pragma unroll
    for (int s = 64; s > 0; s >>= 1) { if (tid < s) red[tid] = fmaxf(red[tid], red[tid+s]); __syncthreads(); }
    mx = red[0]; __syncthreads();

    float sum = 0.f;
    for (int c = 0; c < cnt; c++) { vals[c] = expf(vals[c] - mx); sum += vals[c]; }
    red[tid] = sum; __syncthreads();
    #pragma unroll
    for (int s = 64; s > 0; s >>= 1) { if (tid < s) red[tid] += red[tid+s]; __syncthreads(); }
    const float inv = 1.0f / red[0];

    cnt = 0;
    for (int j = tid; j < n; j += 128) {
        float pv = vals[cnt++] * inv;
        unsigned h, l; split2(pv, h, l);
        g_ph[off + j] = h; g_pl[off + j] = l;
    }
    const int nend = ((i >> 7) + 1) << 7;
    for (int j = n + tid; j < nend; j += 128) { g_ph[off + j] = 0u; g_pl[off + j] = 0u; }
}

// ================================ launch ======================================
extern "C" void kernel_launch(void* const* d_in, const int* in_sizes, int n_in,
                              void* d_out, int out_size) {
    const float* x    = (const float*)d_in[0];
    const float* Wq   = (const float*)d_in[1];
    const float* Wk   = (const float*)d_in[2];
    const float* Wv   = (const float*)d_in[3];
    const float* Wo   = (const float*)d_in[4];
    const float* gain = (const float*)d_in[5];
    float* out = (float*)d_out;

    static int attr_done = 0;
    if (!attr_done) {
        cudaFuncSetAttribute(k_gemm,   cudaFuncAttributeMaxDynamicSharedMemorySize, SMEM_BYTES);
        cudaFuncSetAttribute(k_scores, cudaFuncAttributeMaxDynamicSharedMemorySize, SMEM_BYTES);
        cudaFuncSetAttribute(k_pv,     cudaFuncAttributeMaxDynamicSharedMemorySize, SMEM_BYTES);
        attr_done = 1;
    }

    unsigned *xh, *xl, *wqh, *wkh, *wvh, *woh, *aoh, *aol;
    float *qp, *kp, *vp;
    cudaGetSymbolAddress((void**)&xh,  g_xh);  cudaGetSymbolAddress((void**)&xl,  g_xl);
    cudaGetSymbolAddress((void**)&wqh, g_wqh);
    cudaGetSymbolAddress((void**)&wkh, g_wkh);
    cudaGetSymbolAddress((void**)&wvh, g_wvh);
    cudaGetSymbolAddress((void**)&woh, g_woh);
    cudaGetSymbolAddress((void**)&aoh, g_aoh); cudaGetSymbolAddress((void**)&aol, g_aol);
    cudaGetSymbolAddress((void**)&qp,  g_qp);
    cudaGetSymbolAddress((void**)&kp,  g_kp);
    cudaGetSymbolAddress((void**)&vp,  g_vp);

    // operand prep
    split_kernel<<<(TOK*DIM)/1024, 256>>>(x, xh, xl);
    splithi_kernel<<<(DIM*DIM)/1024, 256>>>(Wq, wqh);
    splithi_kernel<<<(KVD*DIM)/1024, 256>>>(Wk, wkh);
    splithi_kernel<<<(KVD*DIM)/1024, 256>>>(Wv, wvh);
    splithi_kernel<<<(DIM*DIM)/1024, 256>>>(Wo, woh);

    // projections
    k_gemm<<<dim3(DIM/128, TOK/128), 256, SMEM_BYTES>>>(xh, xl, wqh, qp, DIM, DIM, DIM, DIM);
    k_gemm<<<dim3(KVD/128, TOK/128), 256, SMEM_BYTES>>>(xh, xl, wkh, kp, DIM, DIM, KVD, DIM);
    k_gemm<<<dim3(KVD/128, TOK/128), 256, SMEM_BYTES>>>(xh, xl, wvh, vp, DIM, DIM, KVD, DIM);

    // norm + rope + V transpose
    qnorm_kernel<<<(NBH*SEQ*32)/256, 256>>>(gain);
    knorm_kernel<<<(BSZ*NKV*SEQ*32)/256, 256>>>();
    vtrans_kernel<<<dim3(SEQ/32, KVD/32, BSZ), dim3(32, 8)>>>();

    // attention
    k_scores<<<dim3(SEQ/128, SEQ/128, NBH), 256, SMEM_BYTES>>>();
    softmax_kernel<<<NBH*SEQ, 128>>>();
    k_pv<<<dim3(1, SEQ/128, NBH), 256, SMEM_BYTES>>>();

    // output projection
    k_gemm<<<dim3(DIM/128, TOK/128), 256, SMEM_BYTES>>>(aoh, aol, woh, out, DIM, DIM, DIM, DIM);
}

// round 7
// speedup vs baseline: 2.6621x; 1.1525x over previous
#include <cuda_runtime.h>
#include <math.h>

#define BSZ 4
#define SEQ 2048
#define DIM 2048
#define NH  16
#define NKV 4
#define HD  128
#define KVD 512
#define TOK (BSZ*SEQ)          // 8192
#define NBH (BSZ*NH)           // 64
#define REP (NH/NKV)           // 4

// -------- scratch (device globals; no allocation allowed) --------
__device__ unsigned g_xh [(size_t)TOK*DIM],  g_xl [(size_t)TOK*DIM];
__device__ unsigned g_wqh[(size_t)DIM*DIM];
__device__ unsigned g_wkh[(size_t)KVD*DIM];
__device__ unsigned g_wvh[(size_t)KVD*DIM];
__device__ unsigned g_woh[(size_t)DIM*DIM];
__device__ unsigned g_qth[(size_t)BSZ*NH*SEQ*HD];                         // Q hi (norm+rope+gain*scale)
__device__ unsigned g_kth[(size_t)BSZ*NKV*SEQ*HD], g_ktl[(size_t)BSZ*NKV*SEQ*HD]; // K hi+lo
__device__ unsigned g_vth[(size_t)BSZ*NKV*HD*SEQ];                        // V^T hi [b,kh,d,s]
__device__ unsigned g_aoh[(size_t)TOK*DIM],  g_aol[(size_t)TOK*DIM];      // attn out split
__device__ float g_qp[(size_t)TOK*DIM];
__device__ float g_kp[(size_t)TOK*KVD];
__device__ float g_vp[(size_t)TOK*KVD];

// ===================== tf32 helpers =====================
__device__ __forceinline__ unsigned f2tf(float x) {
    unsigned r; asm("cvt.rna.tf32.f32 %0, %1;" : "=r"(r) : "f"(x)); return r;
}
__device__ __forceinline__ void split2(float x, unsigned& h, unsigned& l) {
    h = f2tf(x); l = f2tf(x - __uint_as_float(h));
}

__device__ __forceinline__ void mma8(float* c, const unsigned* a, unsigned b0, unsigned b1) {
    asm volatile(
        "mma.sync.aligned.m16n8k8.row.col.f32.tf32.tf32.f32 "
        "{%0,%1,%2,%3}, {%4,%5,%6,%7}, {%8,%9}, {%0,%1,%2,%3};"
        : "+f"(c[0]), "+f"(c[1]), "+f"(c[2]), "+f"(c[3])
        : "r"(a[0]), "r"(a[1]), "r"(a[2]), "r"(a[3]), "r"(b0), "r"(b1));
}

__device__ __forceinline__ void cpa16(unsigned saddr, const unsigned* g) {
    asm volatile("cp.async.cg.shared.global [%0], [%1], 16;" :: "r"(saddr), "l"(g) : "memory");
}

// =============== projection GEMM (unchanged from R6) ===============
#define LDSTRIDE 20
#define SMTILE   (128*LDSTRIDE)
#define SMBUF    (3*SMTILE)
#define SMEM_BYTES (2*SMBUF*4)    // 61440

__global__ void __launch_bounds__(256, 2) k_gemm(
    const unsigned* __restrict__ Ahg, const unsigned* __restrict__ Alg,
    const unsigned* __restrict__ Bhg,
    float* __restrict__ C, int lda, int ldb, int ldc, int K)
{
    extern __shared__ unsigned sm[];
    Ahg += (size_t)blockIdx.y*128*lda;
    Alg += (size_t)blockIdx.y*128*lda;
    Bhg += (size_t)blockIdx.x*128*ldb;
    C   += (size_t)blockIdx.y*128*ldc + blockIdx.x*128;

    const int tid  = threadIdx.x;
    const int lane = tid & 31;
    const int wid  = tid >> 5;
    const int wm   = wid >> 1;
    const int wn   = wid & 1;
    const int gID  = lane >> 2;
    const int tig  = lane & 3;
    const int r0   = tid >> 2;
    const int r1   = r0 + 64;
    const int kq   = (tid & 3) << 2;
    const unsigned sbase = (unsigned)__cvta_generic_to_shared(sm);

    float c[2][8][4];
    #pragma unroll
    for (int i = 0; i < 2; i++)
        #pragma unroll
        for (int j = 0; j < 8; j++)
            #pragma unroll
            for (int q = 0; q < 4; q++) c[i][j][q] = 0.f;

    {
        unsigned s = sbase;
        cpa16(s + (r0*LDSTRIDE + kq)*4,            Ahg + (size_t)r0*lda + kq);
        cpa16(s + (r1*LDSTRIDE + kq)*4,            Ahg + (size_t)r1*lda + kq);
        cpa16(s + (SMTILE + r0*LDSTRIDE + kq)*4,   Alg + (size_t)r0*lda + kq);
        cpa16(s + (SMTILE + r1*LDSTRIDE + kq)*4,   Alg + (size_t)r1*lda + kq);
        cpa16(s + (2*SMTILE + r0*LDSTRIDE + kq)*4, Bhg + (size_t)r0*ldb + kq);
        cpa16(s + (2*SMTILE + r1*LDSTRIDE + kq)*4, Bhg + (size_t)r1*ldb + kq);
        asm volatile("cp.async.commit_group;" ::: "memory");
    }

    const int T = K >> 4;
    for (int t = 0; t < T; t++) {
        const bool more = (t + 1) < T;
        if (more) {
            int kt = (t+1) << 4;
            unsigned s = sbase + (unsigned)((t+1)&1) * (SMBUF*4);
            cpa16(s + (r0*LDSTRIDE + kq)*4,            Ahg + (size_t)r0*lda + kt + kq);
            cpa16(s + (r1*LDSTRIDE + kq)*4,            Ahg + (size_t)r1*lda + kt + kq);
            cpa16(s + (SMTILE + r0*LDSTRIDE + kq)*4,   Alg + (size_t)r0*lda + kt + kq);
            cpa16(s + (SMTILE + r1*LDSTRIDE + kq)*4,   Alg + (size_t)r1*lda + kt + kq);
            cpa16(s + (2*SMTILE + r0*LDSTRIDE + kq)*4, Bhg + (size_t)r0*ldb + kt + kq);
            cpa16(s + (2*SMTILE + r1*LDSTRIDE + kq)*4, Bhg + (size_t)r1*ldb + kt + kq);
            asm volatile("cp.async.commit_group;" ::: "memory");
            asm volatile("cp.async.wait_group 1;" ::: "memory");
        } else {
            asm volatile("cp.async.wait_group 0;" ::: "memory");
        }
        __syncthreads();

        const unsigned* Ahs = sm + (t&1)*SMBUF;
        const unsigned* Als = Ahs + SMTILE;
        const unsigned* Bhs = Ahs + 2*SMTILE;

        #pragma unroll
        for (int kk = 0; kk < 16; kk += 8) {
            unsigned ah[2][4], al[2][4];
            #pragma unroll
            for (int mt = 0; mt < 2; mt++) {
                int row = wm*32 + mt*16 + gID;
                int col = kk + tig;
                ah[mt][0] = Ahs[row*LDSTRIDE + col];
                ah[mt][1] = Ahs[(row+8)*LDSTRIDE + col];
                ah[mt][2] = Ahs[row*LDSTRIDE + col + 4];
                ah[mt][3] = Ahs[(row+8)*LDSTRIDE + col + 4];
                al[mt][0] = Als[row*LDSTRIDE + col];
                al[mt][1] = Als[(row+8)*LDSTRIDE + col];
                al[mt][2] = Als[row*LDSTRIDE + col + 4];
                al[mt][3] = Als[(row+8)*LDSTRIDE + col + 4];
            }
            #pragma unroll
            for (int nt = 0; nt < 8; nt++) {
                int n = wn*64 + nt*8 + gID;
                int k = kk + tig;
                unsigned bh0 = Bhs[n*LDSTRIDE + k], bh1 = Bhs[n*LDSTRIDE + k + 4];
                #pragma unroll
                for (int mt = 0; mt < 2; mt++) {
                    mma8(c[mt][nt], ah[mt], bh0, bh1);
                    mma8(c[mt][nt], al[mt], bh0, bh1);
                }
            }
        }
        __syncthreads();
    }

    #pragma unroll
    for (int mt = 0; mt < 2; mt++) {
        int row = wm*32 + mt*16 + gID;
        #pragma unroll
        for (int nt = 0; nt < 8; nt++) {
            int col = wn*64 + nt*8 + tig*2;
            *(float2*)&C[(size_t)row*ldc + col]     = make_float2(c[mt][nt][0], c[mt][nt][1]);
            *(float2*)&C[(size_t)(row+8)*ldc + col] = make_float2(c[mt][nt][2], c[mt][nt][3]);
        }
    }
}

// ========================= fused flash attention =========================
// grid (SEQ/128, NBH); 256 threads; smem 230400B
#define SWZ128(r,c) (((r)<<7) + ((c) ^ (((r)&7)<<2)))
#define SWZ64(r,c)  (((r)<<6) + ((c) ^ (((r)&7)<<2)))
#define FLASH_SMEM 230400

__global__ void __launch_bounds__(256, 1) k_flash() {
    extern __shared__ unsigned sm[];
    unsigned* Qs  = sm;            // [128][128] swizzled (hd)
    unsigned* Khs = sm + 16384;    // [64][128]
    unsigned* Kls = sm + 24576;    // [64][128]
    unsigned* Vs  = sm + 32768;    // [128 d][64 s]
    unsigned* Phs = sm + 40960;    // [128][64]
    unsigned* Pls = sm + 49152;    // [128][64]
    float*    red = (float*)(sm + 57344);   // [2][128]

    const int i0 = blockIdx.x * 128;
    const int bh = blockIdx.y;
    const int b = bh / NH, h = bh % NH;
    const unsigned* Qg  = g_qth + (size_t)bh*SEQ*HD + (size_t)i0*HD;
    const size_t kvo = (size_t)(b*NKV + h/REP)*SEQ*HD;
    const unsigned* Khg = g_kth + kvo;
    const unsigned* Klg = g_ktl + kvo;
    const unsigned* Vg  = g_vth + (size_t)(b*NKV + h/REP)*HD*SEQ;

    const int tid  = threadIdx.x;
    const int lane = tid & 31;
    const int wid  = tid >> 5;
    const int wm   = wid >> 1;   // 0..3 (q-row band)
    const int wn   = wid & 1;    // 0..1
    const int gID  = lane >> 2;
    const int tig  = lane & 3;
    const unsigned sb = (unsigned)__cvta_generic_to_shared(sm);

    // ---- load Q (group) ----
    #pragma unroll
    for (int i = 0; i < 16; i++) {
        int idx = tid + i*256;
        int r = idx >> 5, cc = (idx & 31) << 2;
        cpa16(sb + (unsigned)SWZ128(r, cc)*4u, Qg + (size_t)r*HD + cc);
    }
    asm volatile("cp.async.commit_group;" ::: "memory");

    const int JT = i0/64 + 2;

    // ---- prefetch K(0), V(0) ----
    #pragma unroll
    for (int i = 0; i < 8; i++) {
        int idx = tid + i*256;
        int r = idx >> 5, cc = (idx & 31) << 2;
        cpa16(sb + (unsigned)(16384 + SWZ128(r, cc))*4u, Khg + (size_t)r*HD + cc);
        cpa16(sb + (unsigned)(24576 + SWZ128(r, cc))*4u, Klg + (size_t)r*HD + cc);
    }
    asm volatile("cp.async.commit_group;" ::: "memory");
    #pragma unroll
    for (int i = 0; i < 8; i++) {
        int idx = tid + i*256;
        int r = idx >> 4, cc = (idx & 15) << 2;
        cpa16(sb + (unsigned)(32768 + SWZ64(r, cc))*4u, Vg + (size_t)r*SEQ + cc);
    }
    asm volatile("cp.async.commit_group;" ::: "memory");

    float o[2][8][4];
    #pragma unroll
    for (int mt = 0; mt < 2; mt++)
        #pragma unroll
        for (int nt = 0; nt < 8; nt++)
            #pragma unroll
            for (int q = 0; q < 4; q++) o[mt][nt][q] = 0.f;
    float M[2][2] = {{-INFINITY, -INFINITY}, {-INFINITY, -INFINITY}};
    float L[2][2] = {{0.f, 0.f}, {0.f, 0.f}};

    for (int jt = 0; jt < JT; jt++) {
        const int j0 = jt * 64;
        asm volatile("cp.async.wait_group 1;" ::: "memory");
        __syncthreads();                                   // (a) K(jt) ready

        // ---- S = Q K^T (Q_hi * (K_hi + K_lo)) ----
        float cS[2][4][4];
        #pragma unroll
        for (int mt = 0; mt < 2; mt++)
            #pragma unroll
            for (int nt = 0; nt < 4; nt++)
                #pragma unroll
                for (int q = 0; q < 4; q++) cS[mt][nt][q] = 0.f;

        #pragma unroll
        for (int kk = 0; kk < 128; kk += 8) {
            unsigned aq[2][4];
            #pragma unroll
            for (int mt = 0; mt < 2; mt++) {
                int row = wm*32 + mt*16 + gID;
                int col = kk + tig;
                aq[mt][0] = Qs[SWZ128(row,   col)];
                aq[mt][1] = Qs[SWZ128(row+8, col)];
                aq[mt][2] = Qs[SWZ128(row,   col+4)];
                aq[mt][3] = Qs[SWZ128(row+8, col+4)];
            }
            #pragma unroll
            for (int nt = 0; nt < 4; nt++) {
                int n = wn*32 + nt*8 + gID;
                int k = kk + tig;
                unsigned bh0 = Khs[SWZ128(n, k)], bh1 = Khs[SWZ128(n, k+4)];
                unsigned bl0 = Kls[SWZ128(n, k)], bl1 = Kls[SWZ128(n, k+4)];
                #pragma unroll
                for (int mt = 0; mt < 2; mt++) {
                    mma8(cS[mt][nt], aq[mt], bh0, bh1);
                    mma8(cS[mt][nt], aq[mt], bl0, bl1);
                }
            }
        }
        __syncthreads();                                   // (b) done reading K

        if (jt + 1 < JT) {                                 // prefetch K(jt+1)
            int jn = (jt + 1) * 64;
            #pragma unroll
            for (int i = 0; i < 8; i++) {
                int idx = tid + i*256;
                int r = idx >> 5, cc = (idx & 31) << 2;
                cpa16(sb + (unsigned)(16384 + SWZ128(r, cc))*4u, Khg + (size_t)(jn + r)*HD + cc);
                cpa16(sb + (unsigned)(24576 + SWZ128(r, cc))*4u, Klg + (size_t)(jn + r)*HD + cc);
            }
            asm volatile("cp.async.commit_group;" ::: "memory");
        }

        // ---- causal mask + tile row max ----
        float tmx[2][2] = {{-INFINITY, -INFINITY}, {-INFINITY, -INFINITY}};
        #pragma unroll
        for (int mt = 0; mt < 2; mt++)
            #pragma unroll
            for (int nt = 0; nt < 4; nt++)
                #pragma unroll
                for (int q = 0; q < 4; q++) {
                    int gr = i0 + wm*32 + mt*16 + gID + ((q>>1)<<3);
                    int gc = j0 + wn*32 + nt*8 + tig*2 + (q&1);
                    if (gc > gr) cS[mt][nt][q] = -INFINITY;
                    tmx[mt][q>>1] = fmaxf(tmx[mt][q>>1], cS[mt][nt][q]);
                }
        #pragma unroll
        for (int mt = 0; mt < 2; mt++)
            #pragma unroll
            for (int rp = 0; rp < 2; rp++) {
                float v = tmx[mt][rp];
                v = fmaxf(v, __shfl_xor_sync(0xffffffffu, v, 1));
                v = fmaxf(v, __shfl_xor_sync(0xffffffffu, v, 2));
                tmx[mt][rp] = v;
                if (tig == 0) red[wn*128 + wm*32 + mt*16 + gID + rp*8] = v;
            }
        __syncthreads();                                   // (c)

        float alpha[2][2];
        #pragma unroll
        for (int mt = 0; mt < 2; mt++)
            #pragma unroll
            for (int rp = 0; rp < 2; rp++) {
                int rl = wm*32 + mt*16 + gID + rp*8;
                float Mn = fmaxf(M[mt][rp], fmaxf(tmx[mt][rp], red[(1-wn)*128 + rl]));
                alpha[mt][rp] = expf(M[mt][rp] - Mn);
                M[mt][rp] = Mn;
            }

        // ---- P = exp(S - M), write split to smem, tile row sum ----
        float ts[2][2] = {{0.f, 0.f}, {0.f, 0.f}};
        #pragma unroll
        for (int mt = 0; mt < 2; mt++)
            #pragma unroll
            for (int nt = 0; nt < 4; nt++)
                #pragma unroll
                for (int q = 0; q < 4; q++) {
                    int rl = wm*32 + mt*16 + gID + ((q>>1)<<3);
                    int pc = wn*32 + nt*8 + tig*2 + (q&1);
                    float p = expf(cS[mt][nt][q] - M[mt][q>>1]);
                    ts[mt][q>>1] += p;
                    unsigned ph, pl; split2(p, ph, pl);
                    Phs[SWZ64(rl, pc)] = ph;
                    Pls[SWZ64(rl, pc)] = pl;
                }
        // rescale O
        #pragma unroll
        for (int mt = 0; mt < 2; mt++)
            #pragma unroll
            for (int nt = 0; nt < 8; nt++)
                #pragma unroll
                for (int q = 0; q < 4; q++) o[mt][nt][q] *= alpha[mt][q>>1];
        // reduce sums over tig
        #pragma unroll
        for (int mt = 0; mt < 2; mt++)
            #pragma unroll
            for (int rp = 0; rp < 2; rp++) {
                float v = ts[mt][rp];
                v += __shfl_xor_sync(0xffffffffu, v, 1);
                v += __shfl_xor_sync(0xffffffffu, v, 2);
                ts[mt][rp] = v;
            }
        __syncthreads();                                   // (d)
        #pragma unroll
        for (int mt = 0; mt < 2; mt++)
            #pragma unroll
            for (int rp = 0; rp < 2; rp++)
                if (tig == 0) red[wn*128 + wm*32 + mt*16 + gID + rp*8] = ts[mt][rp];
        __syncthreads();                                   // (e)
        #pragma unroll
        for (int mt = 0; mt < 2; mt++)
            #pragma unroll
            for (int rp = 0; rp < 2; rp++) {
                int rl = wm*32 + mt*16 + gID + rp*8;
                L[mt][rp] = L[mt][rp]*alpha[mt][rp] + ts[mt][rp] + red[(1-wn)*128 + rl];
            }

        // ---- wait V(jt) ----
        if (jt + 1 < JT) { asm volatile("cp.async.wait_group 1;" ::: "memory"); }
        else             { asm volatile("cp.async.wait_group 0;" ::: "memory"); }
        __syncthreads();                                   // (f) V + P visible

        // ---- O += P V  ((P_hi + P_lo) * V_hi) ----
        #pragma unroll
        for (int kk = 0; kk < 64; kk += 8) {
            unsigned ap[2][4], al2[2][4];
            #pragma unroll
            for (int mt = 0; mt < 2; mt++) {
                int row = wm*32 + mt*16 + gID;
                int col = kk + tig;
                ap[mt][0]  = Phs[SWZ64(row,   col)];
                ap[mt][1]  = Phs[SWZ64(row+8, col)];
                ap[mt][2]  = Phs[SWZ64(row,   col+4)];
                ap[mt][3]  = Phs[SWZ64(row+8, col+4)];
                al2[mt][0] = Pls[SWZ64(row,   col)];
                al2[mt][1] = Pls[SWZ64(row+8, col)];
                al2[mt][2] = Pls[SWZ64(row,   col+4)];
                al2[mt][3] = Pls[SWZ64(row+8, col+4)];
            }
            #pragma unroll
            for (int nt = 0; nt < 8; nt++) {
                int n = wn*64 + nt*8 + gID;
                int k = kk + tig;
                unsigned bv0 = Vs[SWZ64(n, k)], bv1 = Vs[SWZ64(n, k+4)];
                #pragma unroll
                for (int mt = 0; mt < 2; mt++) {
                    mma8(o[mt][nt], ap[mt],  bv0, bv1);
                    mma8(o[mt][nt], al2[mt], bv0, bv1);
                }
            }
        }
        __syncthreads();                                   // (g) done reading V

        if (jt + 1 < JT) {                                 // prefetch V(jt+1)
            int jn = (jt + 1) * 64;
            #pragma unroll
            for (int i = 0; i < 8; i++) {
                int idx = tid + i*256;
                int r = idx >> 4, cc = (idx & 15) << 2;
                cpa16(sb + (unsigned)(32768 + SWZ64(r, cc))*4u, Vg + (size_t)r*SEQ + jn + cc);
            }
            asm volatile("cp.async.commit_group;" ::: "memory");
        }
    }

    // ---- epilogue: O /= L, write split to g_aoh/g_aol ----
    float inv[2][2];
    #pragma unroll
    for (int mt = 0; mt < 2; mt++)
        #pragma unroll
        for (int rp = 0; rp < 2; rp++) inv[mt][rp] = 1.0f / L[mt][rp];

    #pragma unroll
    for (int mt = 0; mt < 2; mt++) {
        #pragma unroll
        for (int nt = 0; nt < 8; nt++) {
            int dcol = wn*64 + nt*8 + tig*2;
            #pragma unroll
            for (int rp = 0; rp < 2; rp++) {
                int row = i0 + wm*32 + mt*16 + gID + rp*8;
                size_t base = ((size_t)b*SEQ + row)*DIM + h*HD + dcol;
                float v0 = o[mt][nt][rp*2+0] * inv[mt][rp];
                float v1 = o[mt][nt][rp*2+1] * inv[mt][rp];
                unsigned h0, l0, h1, l1;
                split2(v0, h0, l0); split2(v1, h1, l1);
                *(uint2*)&g_aoh[base] = make_uint2(h0, h1);
                *(uint2*)&g_aol[base] = make_uint2(l0, l1);
            }
        }
    }
}

// ====================== pointwise split kernels ======================
__global__ void split_kernel(const float* __restrict__ src,
                             unsigned* __restrict__ hi, unsigned* __restrict__ lo) {
    size_t i = ((size_t)blockIdx.x * blockDim.x + threadIdx.x) * 4;
    float4 v = *(const float4*)&src[i];
    uint4 h, l;
    split2(v.x, h.x, l.x); split2(v.y, h.y, l.y);
    split2(v.z, h.z, l.z); split2(v.w, h.w, l.w);
    *(uint4*)&hi[i] = h; *(uint4*)&lo[i] = l;
}

__global__ void splithi_kernel(const float* __restrict__ src, unsigned* __restrict__ hi) {
    size_t i = ((size_t)blockIdx.x * blockDim.x + threadIdx.x) * 4;
    float4 v = *(const float4*)&src[i];
    *(uint4*)&hi[i] = make_uint4(f2tf(v.x), f2tf(v.y), f2tf(v.z), f2tf(v.w));
}

// ================= RMSNorm + RoPE (+gain*softmax-scale for q) =================
template<bool WRITE_LO>
__device__ __forceinline__ void norm_rope_warp(const float* __restrict__ src,
                                               unsigned* __restrict__ dsth,
                                               unsigned* __restrict__ dstl,
                                               int s, float mult) {
    const int lane = threadIdx.x & 31;
    float4 xv = *(const float4*)&src[lane * 4];
    float nn[4] = {xv.x, xv.y, xv.z, xv.w};
    float ss = nn[0]*nn[0] + nn[1]*nn[1] + nn[2]*nn[2] + nn[3]*nn[3];
    #pragma unroll
    for (int o = 16; o > 0; o >>= 1) ss += __shfl_xor_sync(0xffffffffu, ss, o);
    const float rms = rsqrtf(ss * (1.0f/128.0f) + 1.1920929e-7f);
    #pragma unroll
    for (int j = 0; j < 4; j++) nn[j] *= rms;

    const bool lo = lane < 16;
    uint4 oh, ol;
    unsigned* ohp = &oh.x; unsigned* olp = &ol.x;
    #pragma unroll
    for (int j = 0; j < 4; j++) {
        float partner = __shfl_xor_sync(0xffffffffu, nn[j], 16);
        int d = lane * 4 + j;
        int fi = lo ? d : d - 64;
        float ang = (float)s * powf(10000.0f, -(float)fi * (1.0f/64.0f));
        float sv, cv;
        sincosf(ang, &sv, &cv);
        float out = lo ? (nn[j]*cv + partner*sv) : (nn[j]*cv - partner*sv);
        out *= mult;
        if (WRITE_LO) split2(out, ohp[j], olp[j]);
        else          ohp[j] = f2tf(out);
    }
    *(uint4*)&dsth[lane * 4] = oh;
    if (WRITE_LO) *(uint4*)&dstl[lane * 4] = ol;
}

__global__ void qnorm_kernel(const float* __restrict__ gain) {
    int wid = (blockIdx.x * blockDim.x + threadIdx.x) >> 5;
    int s = wid % SEQ;
    int bh = wid / SEQ;
    int b = bh / NH, h = bh % NH;
    const float* src = g_qp + (size_t)(b*SEQ + s) * DIM + h*HD;
    size_t off = (size_t)bh * SEQ * HD + (size_t)s * HD;
    norm_rope_warp<false>(src, g_qth + off, nullptr, s, gain[h] * 0.08838834764831845f);
}

__global__ void knorm_kernel() {
    int wid = (blockIdx.x * blockDim.x + threadIdx.x) >> 5;
    int s = wid % SEQ;
    int bh = wid / SEQ;
    int b = bh / NKV, h = bh % NKV;
    const float* src = g_kp + (size_t)(b*SEQ + s) * KVD + h*HD;
    size_t off = (size_t)bh * SEQ * HD + (size_t)s * HD;
    norm_rope_warp<true>(src, g_kth + off, g_ktl + off, s, 1.0f);
}

// ============ tiled transpose: g_vp [b,s,(h,d)] -> V^T hi [b,h,d,s] ==========
__global__ void vtrans_kernel() {
    __shared__ float t[32][33];
    const int b  = blockIdx.z;
    const int s0 = blockIdx.x * 32;
    const int c0 = blockIdx.y * 32;
    const int tx = threadIdx.x, ty = threadIdx.y;
    #pragma unroll
    for (int i = 0; i < 4; i++) {
        int row = ty + i*8;
        t[row][tx] = g_vp[((size_t)b*SEQ + s0 + row)*KVD + c0 + tx];
    }
    __syncthreads();
    const int h = c0 >> 7;
    const int dbase = c0 & 127;
    #pragma unroll
    for (int i = 0; i < 4; i++) {
        int row = ty + i*8;
        size_t idx = (((size_t)(b*NKV + h))*HD + dbase + row)*SEQ + s0 + tx;
        g_vth[idx] = f2tf(t[tx][row]);
    }
}

// ================================ launch ======================================
extern "C" void kernel_launch(void* const* d_in, const int* in_sizes, int n_in,
                              void* d_out, int out_size) {
    const float* x    = (const float*)d_in[0];
    const float* Wq   = (const float*)d_in[1];
    const float* Wk   = (const float*)d_in[2];
    const float* Wv   = (const float*)d_in[3];
    const float* Wo   = (const float*)d_in[4];
    const float* gain = (const float*)d_in[5];
    float* out = (float*)d_out;

    static int attr_done = 0;
    if (!attr_done) {
        cudaFuncSetAttribute(k_gemm,  cudaFuncAttributeMaxDynamicSharedMemorySize, SMEM_BYTES);
        cudaFuncSetAttribute(k_flash, cudaFuncAttributeMaxDynamicSharedMemorySize, FLASH_SMEM);
        attr_done = 1;
    }

    unsigned *xh, *xl, *wqh, *wkh, *wvh, *woh, *aoh, *aol;
    float *qp, *kp, *vp;
    cudaGetSymbolAddress((void**)&xh,  g_xh);  cudaGetSymbolAddress((void**)&xl,  g_xl);
    cudaGetSymbolAddress((void**)&wqh, g_wqh);
    cudaGetSymbolAddress((void**)&wkh, g_wkh);
    cudaGetSymbolAddress((void**)&wvh, g_wvh);
    cudaGetSymbolAddress((void**)&woh, g_woh);
    cudaGetSymbolAddress((void**)&aoh, g_aoh); cudaGetSymbolAddress((void**)&aol, g_aol);
    cudaGetSymbolAddress((void**)&qp,  g_qp);
    cudaGetSymbolAddress((void**)&kp,  g_kp);
    cudaGetSymbolAddress((void**)&vp,  g_vp);

    // operand prep
    split_kernel<<<(TOK*DIM)/1024, 256>>>(x, xh, xl);
    splithi_kernel<<<(DIM*DIM)/1024, 256>>>(Wq, wqh);
    splithi_kernel<<<(KVD*DIM)/1024, 256>>>(Wk, wkh);
    splithi_kernel<<<(KVD*DIM)/1024, 256>>>(Wv, wvh);
    splithi_kernel<<<(DIM*DIM)/1024, 256>>>(Wo, woh);

    // projections
    k_gemm<<<dim3(DIM/128, TOK/128), 256, SMEM_BYTES>>>(xh, xl, wqh, qp, DIM, DIM, DIM, DIM);
    k_gemm<<<dim3(KVD/128, TOK/128), 256, SMEM_BYTES>>>(xh, xl, wkh, kp, DIM, DIM, KVD, DIM);
    k_gemm<<<dim3(KVD/128, TOK/128), 256, SMEM_BYTES>>>(xh, xl, wvh, vp, DIM, DIM, KVD, DIM);

    // norm + rope + V transpose
    qnorm_kernel<<<(NBH*SEQ*32)/256, 256>>>(gain);
    knorm_kernel<<<(BSZ*NKV*SEQ*32)/256, 256>>>();
    vtrans_kernel<<<dim3(SEQ/32, KVD/32, BSZ), dim3(32, 8)>>>();

    // fused attention (scores + softmax + PV)
    k_flash<<<dim3(SEQ/128, NBH), 256, FLASH_SMEM>>>();

    // output projection
    k_gemm<<<dim3(DIM/128, TOK/128), 256, SMEM_BYTES>>>(aoh, aol, woh, out, DIM, DIM, DIM, DIM);
}

// round 8
// speedup vs baseline: 3.1920x; 1.1990x over previous
#include <cuda_runtime.h>
#include <cuda_bf16.h>
#include <math.h>

#define BSZ 4
#define SEQ 2048
#define DIM 2048
#define NH  16
#define NKV 4
#define HD  128
#define KVD 512
#define TOK (BSZ*SEQ)          // 8192
#define NBH (BSZ*NH)           // 64
#define REP (NH/NKV)           // 4

// -------- scratch: packed bf16x2 (k-pairs) hi/lo arrays, word = 2 elements ----
__device__ unsigned g_xh [(size_t)TOK*DIM/2],  g_xl [(size_t)TOK*DIM/2];
__device__ unsigned g_wqh[(size_t)DIM*DIM/2],  g_wql[(size_t)DIM*DIM/2];
__device__ unsigned g_wkh[(size_t)KVD*DIM/2],  g_wkl[(size_t)KVD*DIM/2];
__device__ unsigned g_wvh[(size_t)KVD*DIM/2],  g_wvl[(size_t)KVD*DIM/2];
__device__ unsigned g_woh[(size_t)DIM*DIM/2],  g_wol[(size_t)DIM*DIM/2];
__device__ unsigned g_qth[(size_t)BSZ*NH*SEQ*HD/2],  g_qtl[(size_t)BSZ*NH*SEQ*HD/2];
__device__ unsigned g_kth[(size_t)BSZ*NKV*SEQ*HD/2], g_ktl[(size_t)BSZ*NKV*SEQ*HD/2];
__device__ unsigned g_vth[(size_t)BSZ*NKV*HD*SEQ/2], g_vtl[(size_t)BSZ*NKV*HD*SEQ/2];
__device__ unsigned g_aoh[(size_t)TOK*DIM/2],  g_aol[(size_t)TOK*DIM/2];
__device__ float g_qp[(size_t)TOK*DIM];
__device__ float g_kp[(size_t)TOK*KVD];
__device__ float g_vp[(size_t)TOK*KVD];

// ===================== bf16 helpers =====================
__device__ __forceinline__ void bsplit(float x, float& h, float& l) {
    h = __bfloat162float(__float2bfloat16(x));
    l = x - h;
}
// pack two floats into bf16x2 word: v0 -> low half (even k), v1 -> high half
__device__ __forceinline__ unsigned pack2(float v0, float v1) {
    unsigned r;
    asm("cvt.rn.bf16x2.f32 %0, %1, %2;" : "=r"(r) : "f"(v1), "f"(v0));
    return r;
}

__device__ __forceinline__ void mma16(float* c, const unsigned* a, unsigned b0, unsigned b1) {
    asm volatile(
        "mma.sync.aligned.m16n8k16.row.col.f32.bf16.bf16.f32 "
        "{%0,%1,%2,%3}, {%4,%5,%6,%7}, {%8,%9}, {%0,%1,%2,%3};"
        : "+f"(c[0]), "+f"(c[1]), "+f"(c[2]), "+f"(c[3])
        : "r"(a[0]), "r"(a[1]), "r"(a[2]), "r"(a[3]), "r"(b0), "r"(b1));
}

__device__ __forceinline__ void cpa16(unsigned saddr, const unsigned* g) {
    asm volatile("cp.async.cg.shared.global [%0], [%1], 16;" :: "r"(saddr), "l"(g) : "memory");
}

// ====== projection GEMM: C = A[128,K] * B[128,K]^T, 3-term bf16, cp.async db ==
// smem: per stage 4 arrays (Ah,Al,Bh,Bl) of 128 rows x 12 words (8 data + 4 pad)
#define GST 12
#define GARR (128*GST)        // 1536 words
#define GBUF (4*GARR)         // 6144 words
#define SMEM_BYTES (2*GBUF*4) // 49152

__global__ void __launch_bounds__(256, 2) k_gemm(
    const unsigned* __restrict__ Ahg, const unsigned* __restrict__ Alg,
    const unsigned* __restrict__ Bhg, const unsigned* __restrict__ Blg,
    float* __restrict__ C, int lda, int ldb, int ldc, int K)
{
    extern __shared__ unsigned sm[];
    Ahg += (size_t)blockIdx.y*128*lda;
    Alg += (size_t)blockIdx.y*128*lda;
    Bhg += (size_t)blockIdx.x*128*ldb;
    Blg += (size_t)blockIdx.x*128*ldb;
    C   += (size_t)blockIdx.y*128*ldc + blockIdx.x*128;

    const int tid  = threadIdx.x;
    const int lane = tid & 31;
    const int wid  = tid >> 5;
    const int wm   = wid >> 1;
    const int wn   = wid & 1;
    const int gID  = lane >> 2;
    const int tig  = lane & 3;
    const unsigned sbase = (unsigned)__cvta_generic_to_shared(sm);

    const int lr   = tid >> 1;        // 0..127 loader row
    const int lw   = (tid & 1) * 4;   // word col 0 or 4

    float c[2][8][4];
    #pragma unroll
    for (int i = 0; i < 2; i++)
        #pragma unroll
        for (int j = 0; j < 8; j++)
            #pragma unroll
            for (int q = 0; q < 4; q++) c[i][j][q] = 0.f;

    // issue one stage: k-tile ktw (word offset), buffer buf
    #define G_ISSUE(buf, ktw) do {                                              \
        unsigned s_ = sbase + (unsigned)(buf)*(GBUF*4);                         \
        cpa16(s_ + (0*GARR + lr*GST + lw)*4, Ahg + (size_t)lr*lda + (ktw) + lw);\
        cpa16(s_ + (1*GARR + lr*GST + lw)*4, Alg + (size_t)lr*lda + (ktw) + lw);\
        cpa16(s_ + (2*GARR + lr*GST + lw)*4, Bhg + (size_t)lr*ldb + (ktw) + lw);\
        cpa16(s_ + (3*GARR + lr*GST + lw)*4, Blg + (size_t)lr*ldb + (ktw) + lw);\
        asm volatile("cp.async.commit_group;" ::: "memory");                    \
    } while (0)

    G_ISSUE(0, 0);
    const int T = K >> 4;
    for (int t = 0; t < T; t++) {
        const bool more = (t + 1) < T;
        if (more) {
            G_ISSUE((t+1)&1, (t+1)*8);
            asm volatile("cp.async.wait_group 1;" ::: "memory");
        } else {
            asm volatile("cp.async.wait_group 0;" ::: "memory");
        }
        __syncthreads();

        const unsigned* Ahs = sm + (t&1)*GBUF;
        const unsigned* Als = Ahs + GARR;
        const unsigned* Bhs = Ahs + 2*GARR;
        const unsigned* Bls = Ahs + 3*GARR;

        unsigned ah[2][4], al[2][4];
        #pragma unroll
        for (int mt = 0; mt < 2; mt++) {
            int row = wm*32 + mt*16 + gID;
            ah[mt][0] = Ahs[row*GST + tig];
            ah[mt][1] = Ahs[(row+8)*GST + tig];
            ah[mt][2] = Ahs[row*GST + tig + 4];
            ah[mt][3] = Ahs[(row+8)*GST + tig + 4];
            al[mt][0] = Als[row*GST + tig];
            al[mt][1] = Als[(row+8)*GST + tig];
            al[mt][2] = Als[row*GST + tig + 4];
            al[mt][3] = Als[(row+8)*GST + tig + 4];
        }
        #pragma unroll
        for (int nt = 0; nt < 8; nt++) {
            int n = wn*64 + nt*8 + gID;
            unsigned bh0 = Bhs[n*GST + tig], bh1 = Bhs[n*GST + tig + 4];
            unsigned bl0 = Bls[n*GST + tig], bl1 = Bls[n*GST + tig + 4];
            #pragma unroll
            for (int mt = 0; mt < 2; mt++) {
                mma16(c[mt][nt], ah[mt], bh0, bh1);   // hi*hi
                mma16(c[mt][nt], al[mt], bh0, bh1);   // lo*hi
                mma16(c[mt][nt], ah[mt], bl0, bl1);   // hi*lo
            }
        }
        __syncthreads();
    }

    #pragma unroll
    for (int mt = 0; mt < 2; mt++) {
        int row = wm*32 + mt*16 + gID;
        #pragma unroll
        for (int nt = 0; nt < 8; nt++) {
            int col = wn*64 + nt*8 + tig*2;
            *(float2*)&C[(size_t)row*ldc + col]     = make_float2(c[mt][nt][0], c[mt][nt][1]);
            *(float2*)&C[(size_t)(row+8)*ldc + col] = make_float2(c[mt][nt][2], c[mt][nt][3]);
        }
    }
}

// ========================= fused flash attention =========================
// word offsets in smem (strides: QK rows 68 words, VP rows 36 words)
#define F_QH 0
#define F_QL 8704
#define F_KH 17408
#define F_KL 21760
#define F_VH 26112
#define F_VL 30720
#define F_PH 35328
#define F_PL 39936
#define F_RED 44544
#define FLASH_SMEM (44800*4)   // 179200 B

__global__ void __launch_bounds__(256, 1) k_flash() {
    extern __shared__ unsigned sm[];
    float* red = (float*)(sm + F_RED);

    const int i0 = blockIdx.x * 128;
    const int bh = blockIdx.y;
    const int b = bh / NH, h = bh % NH;
    const unsigned* Qhg = g_qth + (size_t)bh*SEQ*64 + (size_t)i0*64;
    const unsigned* Qlg = g_qtl + (size_t)bh*SEQ*64 + (size_t)i0*64;
    const size_t kvo = (size_t)(b*NKV + h/REP)*SEQ*64;
    const unsigned* Khg = g_kth + kvo;
    const unsigned* Klg = g_ktl + kvo;
    const size_t vo = (size_t)(b*NKV + h/REP)*HD*(SEQ/2);
    const unsigned* Vhg = g_vth + vo;
    const unsigned* Vlg = g_vtl + vo;

    const int tid  = threadIdx.x;
    const int lane = tid & 31;
    const int wid  = tid >> 5;
    const int wm   = wid >> 1;
    const int wn   = wid & 1;
    const int gID  = lane >> 2;
    const int tig  = lane & 3;
    const unsigned sb = (unsigned)__cvta_generic_to_shared(sm);

    // ---- load Q hi+lo ----
    #pragma unroll
    for (int i = 0; i < 8; i++) {
        int idx = tid + i*256;
        int r = idx >> 4, seg = (idx & 15) << 2;
        cpa16(sb + (unsigned)(F_QH + r*68 + seg)*4u, Qhg + (size_t)r*64 + seg);
        cpa16(sb + (unsigned)(F_QL + r*68 + seg)*4u, Qlg + (size_t)r*64 + seg);
    }
    asm volatile("cp.async.commit_group;" ::: "memory");

    const int JT = i0/64 + 2;

    // ---- prefetch K(0), V(0) ----
    #pragma unroll
    for (int i = 0; i < 4; i++) {
        int idx = tid + i*256;
        int r = idx >> 4, seg = (idx & 15) << 2;
        cpa16(sb + (unsigned)(F_KH + r*68 + seg)*4u, Khg + (size_t)r*64 + seg);
        cpa16(sb + (unsigned)(F_KL + r*68 + seg)*4u, Klg + (size_t)r*64 + seg);
    }
    asm volatile("cp.async.commit_group;" ::: "memory");
    #pragma unroll
    for (int i = 0; i < 4; i++) {
        int idx = tid + i*256;
        int r = idx >> 3, seg = (idx & 7) << 2;
        cpa16(sb + (unsigned)(F_VH + r*36 + seg)*4u, Vhg + (size_t)r*(SEQ/2) + seg);
        cpa16(sb + (unsigned)(F_VL + r*36 + seg)*4u, Vlg + (size_t)r*(SEQ/2) + seg);
    }
    asm volatile("cp.async.commit_group;" ::: "memory");

    float o[2][8][4];
    #pragma unroll
    for (int mt = 0; mt < 2; mt++)
        #pragma unroll
        for (int nt = 0; nt < 8; nt++)
            #pragma unroll
            for (int q = 0; q < 4; q++) o[mt][nt][q] = 0.f;
    float M[2][2] = {{-INFINITY, -INFINITY}, {-INFINITY, -INFINITY}};
    float L[2][2] = {{0.f, 0.f}, {0.f, 0.f}};

    for (int jt = 0; jt < JT; jt++) {
        const int j0 = jt * 64;
        asm volatile("cp.async.wait_group 1;" ::: "memory");
        __syncthreads();                                   // K(jt) + Q ready

        // ---- S = Q K^T : Qh*Kh + Ql*Kh + Qh*Kl ----
        float cS[2][4][4];
        #pragma unroll
        for (int mt = 0; mt < 2; mt++)
            #pragma unroll
            for (int nt = 0; nt < 4; nt++)
                #pragma unroll
                for (int q = 0; q < 4; q++) cS[mt][nt][q] = 0.f;

        #pragma unroll
        for (int kw = 0; kw < 64; kw += 8) {              // 8 x k16
            unsigned aqh[2][4], aql[2][4];
            #pragma unroll
            for (int mt = 0; mt < 2; mt++) {
                int row = wm*32 + mt*16 + gID;
                int cc = kw + tig;
                aqh[mt][0] = sm[F_QH + row*68 + cc];
                aqh[mt][1] = sm[F_QH + (row+8)*68 + cc];
                aqh[mt][2] = sm[F_QH + row*68 + cc + 4];
                aqh[mt][3] = sm[F_QH + (row+8)*68 + cc + 4];
                aql[mt][0] = sm[F_QL + row*68 + cc];
                aql[mt][1] = sm[F_QL + (row+8)*68 + cc];
                aql[mt][2] = sm[F_QL + row*68 + cc + 4];
                aql[mt][3] = sm[F_QL + (row+8)*68 + cc + 4];
            }
            #pragma unroll
            for (int nt = 0; nt < 4; nt++) {
                int n = wn*32 + nt*8 + gID;
                int cc = kw + tig;
                unsigned bh0 = sm[F_KH + n*68 + cc], bh1 = sm[F_KH + n*68 + cc + 4];
                unsigned bl0 = sm[F_KL + n*68 + cc], bl1 = sm[F_KL + n*68 + cc + 4];
                #pragma unroll
                for (int mt = 0; mt < 2; mt++) {
                    mma16(cS[mt][nt], aqh[mt], bh0, bh1);
                    mma16(cS[mt][nt], aql[mt], bh0, bh1);
                    mma16(cS[mt][nt], aqh[mt], bl0, bl1);
                }
            }
        }
        __syncthreads();                                   // done reading K

        if (jt + 1 < JT) {                                 // prefetch K(jt+1)
            int jn = (jt + 1) * 64;
            #pragma unroll
            for (int i = 0; i < 4; i++) {
                int idx = tid + i*256;
                int r = idx >> 4, seg = (idx & 15) << 2;
                cpa16(sb + (unsigned)(F_KH + r*68 + seg)*4u, Khg + (size_t)(jn + r)*64 + seg);
                cpa16(sb + (unsigned)(F_KL + r*68 + seg)*4u, Klg + (size_t)(jn + r)*64 + seg);
            }
            asm volatile("cp.async.commit_group;" ::: "memory");
        }

        // ---- causal mask + row max ----
        float tmx[2][2] = {{-INFINITY, -INFINITY}, {-INFINITY, -INFINITY}};
        #pragma unroll
        for (int mt = 0; mt < 2; mt++)
            #pragma unroll
            for (int nt = 0; nt < 4; nt++)
                #pragma unroll
                for (int q = 0; q < 4; q++) {
                    int gr = i0 + wm*32 + mt*16 + gID + ((q>>1)<<3);
                    int gc = j0 + wn*32 + nt*8 + tig*2 + (q&1);
                    if (gc > gr) cS[mt][nt][q] = -INFINITY;
                    tmx[mt][q>>1] = fmaxf(tmx[mt][q>>1], cS[mt][nt][q]);
                }
        #pragma unroll
        for (int mt = 0; mt < 2; mt++)
            #pragma unroll
            for (int rp = 0; rp < 2; rp++) {
                float v = tmx[mt][rp];
                v = fmaxf(v, __shfl_xor_sync(0xffffffffu, v, 1));
                v = fmaxf(v, __shfl_xor_sync(0xffffffffu, v, 2));
                tmx[mt][rp] = v;
                if (tig == 0) red[wn*128 + wm*32 + mt*16 + gID + rp*8] = v;
            }
        __syncthreads();

        float alpha[2][2];
        #pragma unroll
        for (int mt = 0; mt < 2; mt++)
            #pragma unroll
            for (int rp = 0; rp < 2; rp++) {
                int rl = wm*32 + mt*16 + gID + rp*8;
                float Mn = fmaxf(M[mt][rp], fmaxf(tmx[mt][rp], red[(1-wn)*128 + rl]));
                alpha[mt][rp] = expf(M[mt][rp] - Mn);
                M[mt][rp] = Mn;
            }

        // ---- P = exp(S - M), pack split into smem; row sums ----
        float ts[2][2] = {{0.f, 0.f}, {0.f, 0.f}};
        #pragma unroll
        for (int mt = 0; mt < 2; mt++)
            #pragma unroll
            for (int nt = 0; nt < 4; nt++) {
                int wc = wn*16 + nt*4 + tig;
                int rl0 = wm*32 + mt*16 + gID;
                float p0 = expf(cS[mt][nt][0] - M[mt][0]);
                float p1 = expf(cS[mt][nt][1] - M[mt][0]);
                float p2 = expf(cS[mt][nt][2] - M[mt][1]);
                float p3 = expf(cS[mt][nt][3] - M[mt][1]);
                ts[mt][0] += p0 + p1;
                ts[mt][1] += p2 + p3;
                float h0,l0,h1,l1,h2,l2,h3,l3;
                bsplit(p0,h0,l0); bsplit(p1,h1,l1); bsplit(p2,h2,l2); bsplit(p3,h3,l3);
                sm[F_PH + rl0*36 + wc]     = pack2(h0, h1);
                sm[F_PL + rl0*36 + wc]     = pack2(l0, l1);
                sm[F_PH + (rl0+8)*36 + wc] = pack2(h2, h3);
                sm[F_PL + (rl0+8)*36 + wc] = pack2(l2, l3);
            }
        #pragma unroll
        for (int mt = 0; mt < 2; mt++)
            #pragma unroll
            for (int nt = 0; nt < 8; nt++)
                #pragma unroll
                for (int q = 0; q < 4; q++) o[mt][nt][q] *= alpha[mt][q>>1];
        #pragma unroll
        for (int mt = 0; mt < 2; mt++)
            #pragma unroll
            for (int rp = 0; rp < 2; rp++) {
                float v = ts[mt][rp];
                v += __shfl_xor_sync(0xffffffffu, v, 1);
                v += __shfl_xor_sync(0xffffffffu, v, 2);
                ts[mt][rp] = v;
            }
        __syncthreads();
        #pragma unroll
        for (int mt = 0; mt < 2; mt++)
            #pragma unroll
            for (int rp = 0; rp < 2; rp++)
                if (tig == 0) red[wn*128 + wm*32 + mt*16 + gID + rp*8] = ts[mt][rp];
        __syncthreads();
        #pragma unroll
        for (int mt = 0; mt < 2; mt++)
            #pragma unroll
            for (int rp = 0; rp < 2; rp++) {
                int rl = wm*32 + mt*16 + gID + rp*8;
                L[mt][rp] = L[mt][rp]*alpha[mt][rp] + ts[mt][rp] + red[(1-wn)*128 + rl];
            }

        // ---- wait V(jt) ----
        if (jt + 1 < JT) { asm volatile("cp.async.wait_group 1;" ::: "memory"); }
        else             { asm volatile("cp.async.wait_group 0;" ::: "memory"); }
        __syncthreads();                                   // V + P visible

        // ---- O += P V : Ph*Vh + Pl*Vh + Ph*Vl ----
        #pragma unroll
        for (int kw = 0; kw < 32; kw += 8) {               // 4 x k16
            unsigned aph[2][4], apl[2][4];
            #pragma unroll
            for (int mt = 0; mt < 2; mt++) {
                int row = wm*32 + mt*16 + gID;
                int cc = kw + tig;
                aph[mt][0] = sm[F_PH + row*36 + cc];
                aph[mt][1] = sm[F_PH + (row+8)*36 + cc];
                aph[mt][2] = sm[F_PH + row*36 + cc + 4];
                aph[mt][3] = sm[F_PH + (row+8)*36 + cc + 4];
                apl[mt][0] = sm[F_PL + row*36 + cc];
                apl[mt][1] = sm[F_PL + (row+8)*36 + cc];
                apl[mt][2] = sm[F_PL + row*36 + cc + 4];
                apl[mt][3] = sm[F_PL + (row+8)*36 + cc + 4];
            }
            #pragma unroll
            for (int nt = 0; nt < 8; nt++) {
                int n = wn*64 + nt*8 + gID;
                int cc = kw + tig;
                unsigned bh0 = sm[F_VH + n*36 + cc], bh1 = sm[F_VH + n*36 + cc + 4];
                unsigned bl0 = sm[F_VL + n*36 + cc], bl1 = sm[F_VL + n*36 + cc + 4];
                #pragma unroll
                for (int mt = 0; mt < 2; mt++) {
                    mma16(o[mt][nt], aph[mt], bh0, bh1);
                    mma16(o[mt][nt], apl[mt], bh0, bh1);
                    mma16(o[mt][nt], aph[mt], bl0, bl1);
                }
            }
        }
        __syncthreads();                                   // done reading V

        if (jt + 1 < JT) {                                 // prefetch V(jt+1)
            int jn2 = (jt + 1) * 32;                       // word offset in s
            #pragma unroll
            for (int i = 0; i < 4; i++) {
                int idx = tid + i*256;
                int r = idx >> 3, seg = (idx & 7) << 2;
                cpa16(sb + (unsigned)(F_VH + r*36 + seg)*4u, Vhg + (size_t)r*(SEQ/2) + jn2 + seg);
                cpa16(sb + (unsigned)(F_VL + r*36 + seg)*4u, Vlg + (size_t)r*(SEQ/2) + jn2 + seg);
            }
            asm volatile("cp.async.commit_group;" ::: "memory");
        }
    }

    // ---- epilogue: O /= L, pack split to g_aoh/g_aol ----
    float inv[2][2];
    #pragma unroll
    for (int mt = 0; mt < 2; mt++)
        #pragma unroll
        for (int rp = 0; rp < 2; rp++) inv[mt][rp] = 1.0f / L[mt][rp];

    #pragma unroll
    for (int mt = 0; mt < 2; mt++) {
        #pragma unroll
        for (int nt = 0; nt < 8; nt++) {
            int wc = wn*32 + nt*4 + tig;                   // word col within head
            #pragma unroll
            for (int rp = 0; rp < 2; rp++) {
                int row = i0 + wm*32 + mt*16 + gID + rp*8;
                size_t base = ((size_t)b*SEQ + row)*(DIM/2) + h*64 + wc;
                float v0 = o[mt][nt][rp*2+0] * inv[mt][rp];
                float v1 = o[mt][nt][rp*2+1] * inv[mt][rp];
                float h0,l0,h1,l1;
                bsplit(v0,h0,l0); bsplit(v1,h1,l1);
                g_aoh[base] = pack2(h0, h1);
                g_aol[base] = pack2(l0, l1);
            }
        }
    }
}

// ====================== pointwise split kernel (packed) ======================
__global__ void split_kernel(const float* __restrict__ src,
                             unsigned* __restrict__ hi, unsigned* __restrict__ lo) {
    size_t i = ((size_t)blockIdx.x * blockDim.x + threadIdx.x) * 4;
    float4 v = *(const float4*)&src[i];
    float h0,l0,h1,l1,h2,l2,h3,l3;
    bsplit(v.x,h0,l0); bsplit(v.y,h1,l1); bsplit(v.z,h2,l2); bsplit(v.w,h3,l3);
    *(uint2*)&hi[i>>1] = make_uint2(pack2(h0,h1), pack2(h2,h3));
    *(uint2*)&lo[i>>1] = make_uint2(pack2(l0,l1), pack2(l2,l3));
}

// ================= RMSNorm + RoPE (+gain*softmax-scale for q) =================
__device__ __forceinline__ void norm_rope_warp(const float* __restrict__ src,
                                               unsigned* __restrict__ dsth,
                                               unsigned* __restrict__ dstl,
                                               int s, float mult) {
    const int lane = threadIdx.x & 31;
    float4 xv = *(const float4*)&src[lane * 4];
    float nn[4] = {xv.x, xv.y, xv.z, xv.w};
    float ss = nn[0]*nn[0] + nn[1]*nn[1] + nn[2]*nn[2] + nn[3]*nn[3];
    #pragma unroll
    for (int o = 16; o > 0; o >>= 1) ss += __shfl_xor_sync(0xffffffffu, ss, o);
    const float rms = rsqrtf(ss * (1.0f/128.0f) + 1.1920929e-7f);
    #pragma unroll
    for (int j = 0; j < 4; j++) nn[j] *= rms;

    const bool lo = lane < 16;
    float out[4];
    #pragma unroll
    for (int j = 0; j < 4; j++) {
        float partner = __shfl_xor_sync(0xffffffffu, nn[j], 16);
        int d = lane * 4 + j;
        int fi = lo ? d : d - 64;
        float ang = (float)s * powf(10000.0f, -(float)fi * (1.0f/64.0f));
        float sv, cv;
        sincosf(ang, &sv, &cv);
        out[j] = lo ? (nn[j]*cv + partner*sv) : (nn[j]*cv - partner*sv);
        out[j] *= mult;
    }
    float h0,l0,h1,l1,h2,l2,h3,l3;
    bsplit(out[0],h0,l0); bsplit(out[1],h1,l1); bsplit(out[2],h2,l2); bsplit(out[3],h3,l3);
    *(uint2*)&dsth[lane*2] = make_uint2(pack2(h0,h1), pack2(h2,h3));
    *(uint2*)&dstl[lane*2] = make_uint2(pack2(l0,l1), pack2(l2,l3));
}

__global__ void qnorm_kernel(const float* __restrict__ gain) {
    int wid = (blockIdx.x * blockDim.x + threadIdx.x) >> 5;
    int s = wid % SEQ;
    int bh = wid / SEQ;
    int b = bh / NH, h = bh % NH;
    const float* src = g_qp + (size_t)(b*SEQ + s) * DIM + h*HD;
    size_t off = (size_t)bh * SEQ * 64 + (size_t)s * 64;
    norm_rope_warp(src, g_qth + off, g_qtl + off, s, gain[h] * 0.08838834764831845f);
}

__global__ void knorm_kernel() {
    int wid = (blockIdx.x * blockDim.x + threadIdx.x) >> 5;
    int s = wid % SEQ;
    int bh = wid / SEQ;
    int b = bh / NKV, h = bh % NKV;
    const float* src = g_kp + (size_t)(b*SEQ + s) * KVD + h*HD;
    size_t off = (size_t)bh * SEQ * 64 + (size_t)s * 64;
    norm_rope_warp(src, g_kth + off, g_ktl + off, s, 1.0f);
}

// ===== tiled transpose: g_vp [b,s,(h,d)] -> packed V^T hi/lo [b,h,d,s/2] =====
__global__ void vtrans_kernel() {
    __shared__ float t[32][33];
    const int b  = blockIdx.z;
    const int s0 = blockIdx.x * 32;
    const int c0 = blockIdx.y * 32;
    const int tx = threadIdx.x, ty = threadIdx.y;
    #pragma unroll
    for (int i = 0; i < 4; i++) {
        int row = ty + i*8;
        t[row][tx] = g_vp[((size_t)b*SEQ + s0 + row)*KVD + c0 + tx];
    }
    __syncthreads();
    const int h = c0 >> 7;
    const int dbase = c0 & 127;
    #pragma unroll
    for (int i = 0; i < 4; i++) {
        int row = ty + i*8;                 // d-local
        float v  = t[tx][row];
        float vn = __shfl_down_sync(0xffffffffu, v, 1);
        if ((tx & 1) == 0) {
            float hv,lv,hn,ln;
            bsplit(v,hv,lv); bsplit(vn,hn,ln);
            size_t idx = (((size_t)(b*NKV + h))*HD + dbase + row)*(SEQ/2) + (s0 >> 1) + (tx >> 1);
            g_vth[idx] = pack2(hv, hn);
            g_vtl[idx] = pack2(lv, ln);
        }
    }
}

// ================================ launch ======================================
extern "C" void kernel_launch(void* const* d_in, const int* in_sizes, int n_in,
                              void* d_out, int out_size) {
    const float* x    = (const float*)d_in[0];
    const float* Wq   = (const float*)d_in[1];
    const float* Wk   = (const float*)d_in[2];
    const float* Wv   = (const float*)d_in[3];
    const float* Wo   = (const float*)d_in[4];
    const float* gain = (const float*)d_in[5];
    float* out = (float*)d_out;

    static int attr_done = 0;
    if (!attr_done) {
        cudaFuncSetAttribute(k_gemm,  cudaFuncAttributeMaxDynamicSharedMemorySize, SMEM_BYTES);
        cudaFuncSetAttribute(k_flash, cudaFuncAttributeMaxDynamicSharedMemorySize, FLASH_SMEM);
        attr_done = 1;
    }

    unsigned *xh, *xl, *wqh, *wql, *wkh, *wkl, *wvh, *wvl, *woh, *wol, *aoh, *aol;
    float *qp, *kp, *vp;
    cudaGetSymbolAddress((void**)&xh,  g_xh);  cudaGetSymbolAddress((void**)&xl,  g_xl);
    cudaGetSymbolAddress((void**)&wqh, g_wqh); cudaGetSymbolAddress((void**)&wql, g_wql);
    cudaGetSymbolAddress((void**)&wkh, g_wkh); cudaGetSymbolAddress((void**)&wkl, g_wkl);
    cudaGetSymbolAddress((void**)&wvh, g_wvh); cudaGetSymbolAddress((void**)&wvl, g_wvl);
    cudaGetSymbolAddress((void**)&woh, g_woh); cudaGetSymbolAddress((void**)&wol, g_wol);
    cudaGetSymbolAddress((void**)&aoh, g_aoh); cudaGetSymbolAddress((void**)&aol, g_aol);
    cudaGetSymbolAddress((void**)&qp,  g_qp);
    cudaGetSymbolAddress((void**)&kp,  g_kp);
    cudaGetSymbolAddress((void**)&vp,  g_vp);

    // operand prep (packed bf16 hi/lo)
    split_kernel<<<(TOK*DIM)/1024, 256>>>(x,  xh,  xl);
    split_kernel<<<(DIM*DIM)/1024, 256>>>(Wq, wqh, wql);
    split_kernel<<<(KVD*DIM)/1024, 256>>>(Wk, wkh, wkl);
    split_kernel<<<(KVD*DIM)/1024, 256>>>(Wv, wvh, wvl);
    split_kernel<<<(DIM*DIM)/1024, 256>>>(Wo, woh, wol);

    // projections (word strides = elements/2)
    k_gemm<<<dim3(DIM/128, TOK/128), 256, SMEM_BYTES>>>(xh, xl, wqh, wql, qp, 1024, 1024, DIM, DIM);
    k_gemm<<<dim3(KVD/128, TOK/128), 256, SMEM_BYTES>>>(xh, xl, wkh, wkl, kp, 1024, 1024, KVD, DIM);
    k_gemm<<<dim3(KVD/128, TOK/128), 256, SMEM_BYTES>>>(xh, xl, wvh, wvl, vp, 1024, 1024, KVD, DIM);

    // norm + rope + V transpose
    qnorm_kernel<<<(NBH*SEQ*32)/256, 256>>>(gain);
    knorm_kernel<<<(BSZ*NKV*SEQ*32)/256, 256>>>();
    vtrans_kernel<<<dim3(SEQ/32, KVD/32, BSZ), dim3(32, 8)>>>();

    // fused attention
    k_flash<<<dim3(SEQ/128, NBH), 256, FLASH_SMEM>>>();

    // output projection
    k_gemm<<<dim3(DIM/128, TOK/128), 256, SMEM_BYTES>>>(aoh, aol, woh, wol, out, 1024, 1024, DIM, DIM);
}

// round 16
// speedup vs baseline: 3.2027x; 1.0034x over previous
#include <cuda_runtime.h>
#include <cuda_bf16.h>
#include <math.h>

#define BSZ 4
#define SEQ 2048
#define DIM 2048
#define NH  16
#define NKV 4
#define HD  128
#define KVD 512
#define TOK (BSZ*SEQ)
#define NBH (BSZ*NH)
#define REP (NH/NKV)

// scratch: packed bf16x2 (k-pairs) hi/lo arrays, word = 2 elements
__device__ unsigned g_xh [(size_t)TOK*DIM/2],  g_xl [(size_t)TOK*DIM/2];
__device__ unsigned g_wqh[(size_t)DIM*DIM/2],  g_wql[(size_t)DIM*DIM/2];
__device__ unsigned g_wkh[(size_t)KVD*DIM/2],  g_wkl[(size_t)KVD*DIM/2];
__device__ unsigned g_wvh[(size_t)KVD*DIM/2],  g_wvl[(size_t)KVD*DIM/2];
__device__ unsigned g_woh[(size_t)DIM*DIM/2],  g_wol[(size_t)DIM*DIM/2];
__device__ unsigned g_qth[(size_t)BSZ*NH*SEQ*HD/2],  g_qtl[(size_t)BSZ*NH*SEQ*HD/2];
__device__ unsigned g_kth[(size_t)BSZ*NKV*SEQ*HD/2], g_ktl[(size_t)BSZ*NKV*SEQ*HD/2];
__device__ unsigned g_vth[(size_t)BSZ*NKV*HD*SEQ/2], g_vtl[(size_t)BSZ*NKV*HD*SEQ/2];
__device__ unsigned g_aoh[(size_t)TOK*DIM/2],  g_aol[(size_t)TOK*DIM/2];
__device__ float g_qp[(size_t)TOK*DIM];
__device__ float g_kp[(size_t)TOK*KVD];
__device__ float g_vp[(size_t)TOK*KVD];

// bf16 helpers
__device__ __forceinline__ void bsplit(float x, float& h, float& l) {
    h = __bfloat162float(__float2bfloat16(x));
    l = x - h;
}
__device__ __forceinline__ unsigned pack2(float v0, float v1) {
    unsigned r;
    asm("cvt.rn.bf16x2.f32 %0, %1, %2;" : "=r"(r) : "f"(v1), "f"(v0));
    return r;
}
__device__ __forceinline__ void mma16(float* c, const unsigned* a, unsigned b0, unsigned b1) {
    asm volatile(
        "mma.sync.aligned.m16n8k16.row.col.f32.bf16.bf16.f32 "
        "{%0,%1,%2,%3}, {%4,%5,%6,%7}, {%8,%9}, {%0,%1,%2,%3};"
        : "+f"(c[0]), "+f"(c[1]), "+f"(c[2]), "+f"(c[3])
        : "r"(a[0]), "r"(a[1]), "r"(a[2]), "r"(a[3]), "r"(b0), "r"(b1));
}
__device__ __forceinline__ void cpa16(unsigned saddr, const unsigned* g) {
    asm volatile("cp.async.cg.shared.global [%0], [%1], 16;" :: "r"(saddr), "l"(g) : "memory");
}

// projection GEMM: C = A[128,K] * B[128,K]^T, 3-term bf16, k32 stages, double buffer
#define GST 20
#define GARR (128*GST)
#define GBUF (4*GARR)
#define SMEM_BYTES (2*GBUF*4)

__global__ void __launch_bounds__(256, 2) k_gemm(
    const unsigned* __restrict__ Ahg, const unsigned* __restrict__ Alg,
    const unsigned* __restrict__ Bhg, const unsigned* __restrict__ Blg,
    float* __restrict__ C, int lda, int ldb, int ldc, int K)
{
    extern __shared__ unsigned sm[];
    Ahg += (size_t)blockIdx.y*128*lda;
    Alg += (size_t)blockIdx.y*128*lda;
    Bhg += (size_t)blockIdx.x*128*ldb;
    Blg += (size_t)blockIdx.x*128*ldb;
    C   += (size_t)blockIdx.y*128*ldc + blockIdx.x*128;

    const int tid  = threadIdx.x;
    const int lane = tid & 31;
    const int wid  = tid >> 5;
    const int wm   = wid >> 1;
    const int wn   = wid & 1;
    const int gID  = lane >> 2;
    const int tig  = lane & 3;
    const unsigned sbase = (unsigned)__cvta_generic_to_shared(sm);

    const int lr   = tid >> 1;
    const int lw   = (tid & 1) * 4;

    float c[2][8][4];
    #pragma unroll
    for (int i = 0; i < 2; i++)
        #pragma unroll
        for (int j = 0; j < 8; j++)
            #pragma unroll
            for (int q = 0; q < 4; q++) c[i][j][q] = 0.f;

    #define G_ISSUE(buf, ktw) do {                                                    \
        unsigned s_ = sbase + (unsigned)(buf)*(GBUF*4);                               \
        cpa16(s_ + (0*GARR + lr*GST + lw)*4,     Ahg + (size_t)lr*lda + (ktw) + lw);  \
        cpa16(s_ + (0*GARR + lr*GST + lw + 8)*4, Ahg + (size_t)lr*lda + (ktw) + lw + 8); \
        cpa16(s_ + (1*GARR + lr*GST + lw)*4,     Alg + (size_t)lr*lda + (ktw) + lw);  \
        cpa16(s_ + (1*GARR + lr*GST + lw + 8)*4, Alg + (size_t)lr*lda + (ktw) + lw + 8); \
        cpa16(s_ + (2*GARR + lr*GST + lw)*4,     Bhg + (size_t)lr*ldb + (ktw) + lw);  \
        cpa16(s_ + (2*GARR + lr*GST + lw + 8)*4, Bhg + (size_t)lr*ldb + (ktw) + lw + 8); \
        cpa16(s_ + (3*GARR + lr*GST + lw)*4,     Blg + (size_t)lr*ldb + (ktw) + lw);  \
        cpa16(s_ + (3*GARR + lr*GST + lw + 8)*4, Blg + (size_t)lr*ldb + (ktw) + lw + 8); \
        asm volatile("cp.async.commit_group;" ::: "memory");                          \
    } while (0)

    G_ISSUE(0, 0);
    const int T = K >> 5;
    for (int t = 0; t < T; t++) {
        const bool more = (t + 1) < T;
        if (more) {
            G_ISSUE((t+1)&1, (t+1)*16);
            asm volatile("cp.async.wait_group 1;" ::: "memory");
        } else {
            asm volatile("cp.async.wait_group 0;" ::: "memory");
        }
        __syncthreads();

        const unsigned* Ahs = sm + (t&1)*GBUF;
        const unsigned* Als = Ahs + GARR;
        const unsigned* Bhs = Ahs + 2*GARR;
        const unsigned* Bls = Ahs + 3*GARR;

        #pragma unroll
        for (int kk = 0; kk < 16; kk += 8) {
            unsigned ah[2][4], al[2][4];
            #pragma unroll
            for (int mt = 0; mt < 2; mt++) {
                int row = wm*32 + mt*16 + gID;
                int cc = kk + tig;
                ah[mt][0] = Ahs[row*GST + cc];
                ah[mt][1] = Ahs[(row+8)*GST + cc];
                ah[mt][2] = Ahs[row*GST + cc + 4];
                ah[mt][3] = Ahs[(row+8)*GST + cc + 4];
                al[mt][0] = Als[row*GST + cc];
                al[mt][1] = Als[(row+8)*GST + cc];
                al[mt][2] = Als[row*GST + cc + 4];
                al[mt][3] = Als[(row+8)*GST + cc + 4];
            }
            #pragma unroll
            for (int nt = 0; nt < 8; nt++) {
                int n = wn*64 + nt*8 + gID;
                int cc = kk + tig;
                unsigned bh0 = Bhs[n*GST + cc], bh1 = Bhs[n*GST + cc + 4];
                unsigned bl0 = Bls[n*GST + cc], bl1 = Bls[n*GST + cc + 4];
                #pragma unroll
                for (int mt = 0; mt < 2; mt++) {
                    mma16(c[mt][nt], ah[mt], bh0, bh1);
                    mma16(c[mt][nt], al[mt], bh0, bh1);
                    mma16(c[mt][nt], ah[mt], bl0, bl1);
                }
            }
        }
        __syncthreads();
    }

    #pragma unroll
    for (int mt = 0; mt < 2; mt++) {
        int row = wm*32 + mt*16 + gID;
        #pragma unroll
        for (int nt = 0; nt < 8; nt++) {
            int col = wn*64 + nt*8 + tig*2;
            *(float2*)&C[(size_t)row*ldc + col]     = make_float2(c[mt][nt][0], c[mt][nt][1]);
            *(float2*)&C[(size_t)(row+8)*ldc + col] = make_float2(c[mt][nt][2], c[mt][nt][3]);
        }
    }
}

// fused flash attention
#define F_QH 0
#define F_QL 8704
#define F_KH 17408
#define F_KL 21760
#define F_VH 26112
#define F_VL 30720
#define F_PH 35328
#define F_PL 39936
#define F_RED 44544
#define FLASH_SMEM (44800*4)

__global__ void __launch_bounds__(256, 1) k_flash() {
    extern __shared__ unsigned sm[];
    float* red = (float*)(sm + F_RED);

    const int i0 = blockIdx.x * 128;
    const int bh = blockIdx.y;
    const int b = bh / NH, h = bh % NH;
    const unsigned* Qhg = g_qth + (size_t)bh*SEQ*64 + (size_t)i0*64;
    const unsigned* Qlg = g_qtl + (size_t)bh*SEQ*64 + (size_t)i0*64;
    const size_t kvo = (size_t)(b*NKV + h/REP)*SEQ*64;
    const unsigned* Khg = g_kth + kvo;
    const unsigned* Klg = g_ktl + kvo;
    const size_t vo = (size_t)(b*NKV + h/REP)*HD*(SEQ/2);
    const unsigned* Vhg = g_vth + vo;
    const unsigned* Vlg = g_vtl + vo;

    const int tid  = threadIdx.x;
    const int lane = tid & 31;
    const int wid  = tid >> 5;
    const int wm   = wid >> 1;
    const int wn   = wid & 1;
    const int gID  = lane >> 2;
    const int tig  = lane & 3;
    const unsigned sb = (unsigned)__cvta_generic_to_shared(sm);

    #pragma unroll
    for (int i = 0; i < 8; i++) {
        int idx = tid + i*256;
        int r = idx >> 4, seg = (idx & 15) << 2;
        cpa16(sb + (unsigned)(F_QH + r*68 + seg)*4u, Qhg + (size_t)r*64 + seg);
        cpa16(sb + (unsigned)(F_QL + r*68 + seg)*4u, Qlg + (size_t)r*64 + seg);
    }
    asm volatile("cp.async.commit_group;" ::: "memory");

    const int JT = i0/64 + 2;

    #pragma unroll
    for (int i = 0; i < 4; i++) {
        int idx = tid + i*256;
        int r = idx >> 4, seg = (idx & 15) << 2;
        cpa16(sb + (unsigned)(F_KH + r*68 + seg)*4u, Khg + (size_t)r*64 + seg);
        cpa16(sb + (unsigned)(F_KL + r*68 + seg)*4u, Klg + (size_t)r*64 + seg);
    }
    asm volatile("cp.async.commit_group;" ::: "memory");
    #pragma unroll
    for (int i = 0; i < 4; i++) {
        int idx = tid + i*256;
        int r = idx >> 3, seg = (idx & 7) << 2;
        cpa16(sb + (unsigned)(F_VH + r*36 + seg)*4u, Vhg + (size_t)r*(SEQ/2) + seg);
        cpa16(sb + (unsigned)(F_VL + r*36 + seg)*4u, Vlg + (size_t)r*(SEQ/2) + seg);
    }
    asm volatile("cp.async.commit_group;" ::: "memory");

    float o[2][8][4];
    #pragma unroll
    for (int mt = 0; mt < 2; mt++)
        #pragma unroll
        for (int nt = 0; nt < 8; nt++)
            #pragma unroll
            for (int q = 0; q < 4; q++) o[mt][nt][q] = 0.f;
    float M[2][2] = {{-INFINITY, -INFINITY}, {-INFINITY, -INFINITY}};
    float L[2][2] = {{0.f, 0.f}, {0.f, 0.f}};

    for (int jt = 0; jt < JT; jt++) {
        const int j0 = jt * 64;
        asm volatile("cp.async.wait_group 1;" ::: "memory");
        __syncthreads();

        float cS[2][4][4];
        #pragma unroll
        for (int mt = 0; mt < 2; mt++)
            #pragma unroll
            for (int nt = 0; nt < 4; nt++)
                #pragma unroll
                for (int q = 0; q < 4; q++) cS[mt][nt][q] = 0.f;

        #pragma unroll
        for (int kw = 0; kw < 64; kw += 8) {
            unsigned aqh[2][4], aql[2][4];
            #pragma unroll
            for (int mt = 0; mt < 2; mt++) {
                int row = wm*32 + mt*16 + gID;
                int cc = kw + tig;
                aqh[mt][0] = sm[F_QH + row*68 + cc];
                aqh[mt][1] = sm[F_QH + (row+8)*68 + cc];
                aqh[mt][2] = sm[F_QH + row*68 + cc + 4];
                aqh[mt][3] = sm[F_QH + (row+8)*68 + cc + 4];
                aql[mt][0] = sm[F_QL + row*68 + cc];
                aql[mt][1] = sm[F_QL + (row+8)*68 + cc];
                aql[mt][2] = sm[F_QL + row*68 + cc + 4];
                aql[mt][3] = sm[F_QL + (row+8)*68 + cc + 4];
            }
            #pragma unroll
            for (int nt = 0; nt < 4; nt++) {
                int n = wn*32 + nt*8 + gID;
                int cc = kw + tig;
                unsigned bh0 = sm[F_KH + n*68 + cc], bh1 = sm[F_KH + n*68 + cc + 4];
                unsigned bl0 = sm[F_KL + n*68 + cc], bl1 = sm[F_KL + n*68 + cc + 4];
                #pragma unroll
                for (int mt = 0; mt < 2; mt++) {
                    mma16(cS[mt][nt], aqh[mt], bh0, bh1);
                    mma16(cS[mt][nt], aql[mt], bh0, bh1);
                    mma16(cS[mt][nt], aqh[mt], bl0, bl1);
                }
            }
        }
        __syncthreads();

        if (jt + 1 < JT) {
            int jn = (jt + 1) * 64;
            #pragma unroll
            for (int i = 0; i < 4; i++) {
                int idx = tid + i*256;
                int r = idx >> 4, seg = (idx & 15) << 2;
                cpa16(sb + (unsigned)(F_KH + r*68 + seg)*4u, Khg + (size_t)(jn + r)*64 + seg);
                cpa16(sb + (unsigned)(F_KL + r*68 + seg)*4u, Klg + (size_t)(jn + r)*64 + seg);
            }
            asm volatile("cp.async.commit_group;" ::: "memory");
        }

        float tmx[2][2] = {{-INFINITY, -INFINITY}, {-INFINITY, -INFINITY}};
        #pragma unroll
        for (int mt = 0; mt < 2; mt++)
            #pragma unroll
            for (int nt = 0; nt < 4; nt++)
                #pragma unroll
                for (int q = 0; q < 4; q++) {
                    int gr = i0 + wm*32 + mt*16 + gID + ((q>>1)<<3);
                    int gc = j0 + wn*32 + nt*8 + tig*2 + (q&1);
                    if (gc > gr) cS[mt][nt][q] = -INFINITY;
                    tmx[mt][q>>1] = fmaxf(tmx[mt][q>>1], cS[mt][nt][q]);
                }
        #pragma unroll
        for (int mt = 0; mt < 2; mt++)
            #pragma unroll
            for (int rp = 0; rp < 2; rp++) {
                float v = tmx[mt][rp];
                v = fmaxf(v, __shfl_xor_sync(0xffffffffu, v, 1));
                v = fmaxf(v, __shfl_xor_sync(0xffffffffu, v, 2));
                tmx[mt][rp] = v;
                if (tig == 0) red[wn*128 + wm*32 + mt*16 + gID + rp*8] = v;
            }
        __syncthreads();

        float alpha[2][2];
        #pragma unroll
        for (int mt = 0; mt < 2; mt++)
            #pragma unroll
            for (int rp = 0; rp < 2; rp++) {
                int rl = wm*32 + mt*16 + gID + rp*8;
                float Mn = fmaxf(M[mt][rp], fmaxf(tmx[mt][rp], red[(1-wn)*128 + rl]));
                alpha[mt][rp] = expf(M[mt][rp] - Mn);
                M[mt][rp] = Mn;
            }

        float ts[2][2] = {{0.f, 0.f}, {0.f, 0.f}};
        #pragma unroll
        for (int mt = 0; mt < 2; mt++)
            #pragma unroll
            for (int nt = 0; nt < 4; nt++) {
                int wc = wn*16 + nt*4 + tig;
                int rl0 = wm*32 + mt*16 + gID;
                float p0 = expf(cS[mt][nt][0] - M[mt][0]);
                float p1 = expf(cS[mt][nt][1] - M[mt][0]);
                float p2 = expf(cS[mt][nt][2] - M[mt][1]);
                float p3 = expf(cS[mt][nt][3] - M[mt][1]);
                ts[mt][0] += p0 + p1;
                ts[mt][1] += p2 + p3;
                float h0,l0,h1,l1,h2,l2,h3,l3;
                bsplit(p0,h0,l0); bsplit(p1,h1,l1); bsplit(p2,h2,l2); bsplit(p3,h3,l3);
                sm[F_PH + rl0*36 + wc]     = pack2(h0, h1);
                sm[F_PL + rl0*36 + wc]     = pack2(l0, l1);
                sm[F_PH + (rl0+8)*36 + wc] = pack2(h2, h3);
                sm[F_PL + (rl0+8)*36 + wc] = pack2(l2, l3);
            }
        #pragma unroll
        for (int mt = 0; mt < 2; mt++)
            #pragma unroll
            for (int nt = 0; nt < 8; nt++)
                #pragma unroll
                for (int q = 0; q < 4; q++) o[mt][nt][q] *= alpha[mt][q>>1];
        #pragma unroll
        for (int mt = 0; mt < 2; mt++)
            #pragma unroll
            for (int rp = 0; rp < 2; rp++) {
                float v = ts[mt][rp];
                v += __shfl_xor_sync(0xffffffffu, v, 1);
                v += __shfl_xor_sync(0xffffffffu, v, 2);
                ts[mt][rp] = v;
            }
        __syncthreads();
        #pragma unroll
        for (int mt = 0; mt < 2; mt++)
            #pragma unroll
            for (int rp = 0; rp < 2; rp++)
                if (tig == 0) red[wn*128 + wm*32 + mt*16 + gID + rp*8] = ts[mt][rp];
        __syncthreads();
        #pragma unroll
        for (int mt = 0; mt < 2; mt++)
            #pragma unroll
            for (int rp = 0; rp < 2; rp++) {
                int rl = wm*32 + mt*16 + gID + rp*8;
                L[mt][rp] = L[mt][rp]*alpha[mt][rp] + ts[mt][rp] + red[(1-wn)*128 + rl];
            }

        if (jt + 1 < JT) { asm volatile("cp.async.wait_group 1;" ::: "memory"); }
        else             { asm volatile("cp.async.wait_group 0;" ::: "memory"); }
        __syncthreads();

        #pragma unroll
        for (int kw = 0; kw < 32; kw += 8) {
            unsigned aph[2][4], apl[2][4];
            #pragma unroll
            for (int mt = 0; mt < 2; mt++) {
                int row = wm*32 + mt*16 + gID;
                int cc = kw + tig;
                aph[mt][0] = sm[F_PH + row*36 + cc];
                aph[mt][1] = sm[F_PH + (row+8)*36 + cc];
                aph[mt][2] = sm[F_PH + row*36 + cc + 4];
                aph[mt][3] = sm[F_PH + (row+8)*36 + cc + 4];
                apl[mt][0] = sm[F_PL + row*36 + cc];
                apl[mt][1] = sm[F_PL + (row+8)*36 + cc];
                apl[mt][2] = sm[F_PL + row*36 + cc + 4];
                apl[mt][3] = sm[F_PL + (row+8)*36 + cc + 4];
            }
            #pragma unroll
            for (int nt = 0; nt < 8; nt++) {
                int n = wn*64 + nt*8 + gID;
                int cc = kw + tig;
                unsigned bh0 = sm[F_VH + n*36 + cc], bh1 = sm[F_VH + n*36 + cc + 4];
                unsigned bl0 = sm[F_VL + n*36 + cc], bl1 = sm[F_VL + n*36 + cc + 4];
                #pragma unroll
                for (int mt = 0; mt < 2; mt++) {
                    mma16(o[mt][nt], aph[mt], bh0, bh1);
                    mma16(o[mt][nt], apl[mt], bh0, bh1);
                    mma16(o[mt][nt], aph[mt], bl0, bl1);
                }
            }
        }
        __syncthreads();

        if (jt + 1 < JT) {
            int jn2 = (jt + 1) * 32;
            #pragma unroll
            for (int i = 0; i < 4; i++) {
                int idx = tid + i*256;
                int r = idx >> 3, seg = (idx & 7) << 2;
                cpa16(sb + (unsigned)(F_VH + r*36 + seg)*4u, Vhg + (size_t)r*(SEQ/2) + jn2 + seg);
                cpa16(sb + (unsigned)(F_VL + r*36 + seg)*4u, Vlg + (size_t)r*(SEQ/2) + jn2 + seg);
            }
            asm volatile("cp.async.commit_group;" ::: "memory");
        }
    }

    float inv[2][2];
    #pragma unroll
    for (int mt = 0; mt < 2; mt++)
        #pragma unroll
        for (int rp = 0; rp < 2; rp++) inv[mt][rp] = 1.0f / L[mt][rp];

    #pragma unroll
    for (int mt = 0; mt < 2; mt++) {
        #pragma unroll
        for (int nt = 0; nt < 8; nt++) {
            int wc = wn*32 + nt*4 + tig;
            #pragma unroll
            for (int rp = 0; rp < 2; rp++) {
                int row = i0 + wm*32 + mt*16 + gID + rp*8;
                size_t base = ((size_t)b*SEQ + row)*(DIM/2) + h*64 + wc;
                float v0 = o[mt][nt][rp*2+0] * inv[mt][rp];
                float v1 = o[mt][nt][rp*2+1] * inv[mt][rp];
                float h0,l0,h1,l1;
                bsplit(v0,h0,l0); bsplit(v1,h1,l1);
                g_aoh[base] = pack2(h0, h1);
                g_aol[base] = pack2(l0, l1);
            }
        }
    }
}

// pointwise split kernel (packed)
__global__ void split_kernel(const float* __restrict__ src,
                             unsigned* __restrict__ hi, unsigned* __restrict__ lo) {
    size_t i = ((size_t)blockIdx.x * blockDim.x + threadIdx.x) * 4;
    float4 v = *(const float4*)&src[i];
    float h0,l0,h1,l1,h2,l2,h3,l3;
    bsplit(v.x,h0,l0); bsplit(v.y,h1,l1); bsplit(v.z,h2,l2); bsplit(v.w,h3,l3);
    *(uint2*)&hi[i>>1] = make_uint2(pack2(h0,h1), pack2(h2,h3));
    *(uint2*)&lo[i>>1] = make_uint2(pack2(l0,l1), pack2(l2,l3));
}

// RMSNorm + RoPE (+gain*softmax-scale for q)
__device__ __forceinline__ void norm_rope_warp(const float* __restrict__ src,
                                               unsigned* __restrict__ dsth,
                                               unsigned* __restrict__ dstl,
                                               int s, float mult) {
    const int lane = threadIdx.x & 31;
    float4 xv = *(const float4*)&src[lane * 4];
    float nn[4] = {xv.x, xv.y, xv.z, xv.w};
    float ss = nn[0]*nn[0] + nn[1]*nn[1] + nn[2]*nn[2] + nn[3]*nn[3];
    #pragma unroll
    for (int o = 16; o > 0; o >>= 1) ss += __shfl_xor_sync(0xffffffffu, ss, o);
    const float rms = rsqrtf(ss * (1.0f/128.0f) + 1.1920929e-7f);
    #pragma unroll
    for (int j = 0; j < 4; j++) nn[j] *= rms;

    const bool lo = lane < 16;
    float out[4];
    #pragma unroll
    for (int j = 0; j < 4; j++) {
        float partner = __shfl_xor_sync(0xffffffffu, nn[j], 16);
        int d = lane * 4 + j;
        int fi = lo ? d : d - 64;
        float ang = (float)s * powf(10000.0f, -(float)fi * (1.0f/64.0f));
        float sv, cv;
        sincosf(ang, &sv, &cv);
        out[j] = lo ? (nn[j]*cv + partner*sv) : (nn[j]*cv - partner*sv);
        out[j] *= mult;
    }
    float h0,l0,h1,l1,h2,l2,h3,l3;
    bsplit(out[0],h0,l0); bsplit(out[1],h1,l1); bsplit(out[2],h2,l2); bsplit(out[3],h3,l3);
    *(uint2*)&dsth[lane*2] = make_uint2(pack2(h0,h1), pack2(h2,h3));
    *(uint2*)&dstl[lane*2] = make_uint2(pack2(l0,l1), pack2(l2,l3));
}

__global__ void qnorm_kernel(const float* __restrict__ gain) {
    int wid = (blockIdx.x * blockDim.x + threadIdx.x) >> 5;
    int s = wid % SEQ;
    int bh = wid / SEQ;
    int b = bh / NH, h = bh % NH;
    const float* src = g_qp + (size_t)(b*SEQ + s) * DIM + h*HD;
    size_t off = (size_t)bh * SEQ * 64 + (size_t)s * 64;
    norm_rope_warp(src, g_qth + off, g_qtl + off, s, gain[h] * 0.08838834764831845f);
}

__global__ void knorm_kernel() {
    int wid = (blockIdx.x * blockDim.x + threadIdx.x) >> 5;
    int s = wid % SEQ;
    int bh = wid / SEQ;
    int b = bh / NKV, h = bh % NKV;
    const float* src = g_kp + (size_t)(b*SEQ + s) * KVD + h*HD;
    size_t off = (size_t)bh * SEQ * 64 + (size_t)s * 64;
    norm_rope_warp(src, g_kth + off, g_ktl + off, s, 1.0f);
}

// tiled transpose: g_vp [b,s,(h,d)] to packed V^T hi/lo [b,h,d,s/2]
__global__ void vtrans_kernel() {
    __shared__ float t[32][33];
    const int b  = blockIdx.z;
    const int s0 = blockIdx.x * 32;
    const int c0 = blockIdx.y * 32;
    const int tx = threadIdx.x, ty = threadIdx.y;
    #pragma unroll
    for (int i = 0; i < 4; i++) {
        int row = ty + i*8;
        t[row][tx] = g_vp[((size_t)b*SEQ + s0 + row)*KVD + c0 + tx];
    }
    __syncthreads();
    const int h = c0 >> 7;
    const int dbase = c0 & 127;
    #pragma unroll
    for (int i = 0; i < 4; i++) {
        int row = ty + i*8;
        float v  = t[tx][row];
        float vn = __shfl_down_sync(0xffffffffu, v, 1);
        if ((tx & 1) == 0) {
            float hv,lv,hn,ln;
            bsplit(v,hv,lv); bsplit(vn,hn,ln);
            size_t idx = (((size_t)(b*NKV + h))*HD + dbase + row)*(SEQ/2) + (s0 >> 1) + (tx >> 1);
            g_vth[idx] = pack2(hv, hn);
            g_vtl[idx] = pack2(lv, ln);
        }
    }
}

// launch
extern "C" void kernel_launch(void* const* d_in, const int* in_sizes, int n_in,
                              void* d_out, int out_size) {
    const float* x    = (const float*)d_in[0];
    const float* Wq   = (const float*)d_in[1];
    const float* Wk   = (const float*)d_in[2];
    const float* Wv   = (const float*)d_in[3];
    const float* Wo   = (const float*)d_in[4];
    const float* gain = (const float*)d_in[5];
    float* out = (float*)d_out;

    static int attr_done = 0;
    if (!attr_done) {
        cudaFuncSetAttribute(k_gemm,  cudaFuncAttributeMaxDynamicSharedMemorySize, SMEM_BYTES);
        cudaFuncSetAttribute(k_flash, cudaFuncAttributeMaxDynamicSharedMemorySize, FLASH_SMEM);
        attr_done = 1;
    }

    unsigned *xh, *xl, *wqh, *wql, *wkh, *wkl, *wvh, *wvl, *woh, *wol, *aoh, *aol;
    float *qp, *kp, *vp;
    cudaGetSymbolAddress((void**)&xh,  g_xh);  cudaGetSymbolAddress((void**)&xl,  g_xl);
    cudaGetSymbolAddress((void**)&wqh, g_wqh); cudaGetSymbolAddress((void**)&wql, g_wql);
    cudaGetSymbolAddress((void**)&wkh, g_wkh); cudaGetSymbolAddress((void**)&wkl, g_wkl);
    cudaGetSymbolAddress((void**)&wvh, g_wvh); cudaGetSymbolAddress((void**)&wvl, g_wvl);
    cudaGetSymbolAddress((void**)&woh, g_woh); cudaGetSymbolAddress((void**)&wol, g_wol);
    cudaGetSymbolAddress((void**)&aoh, g_aoh); cudaGetSymbolAddress((void**)&aol, g_aol);
    cudaGetSymbolAddress((void**)&qp,  g_qp);
    cudaGetSymbolAddress((void**)&kp,  g_kp);
    cudaGetSymbolAddress((void**)&vp,  g_vp);

    split_kernel<<<(TOK*DIM)/1024, 256>>>(x,  xh,  xl);
    split_kernel<<<(DIM*DIM)/1024, 256>>>(Wq, wqh, wql);
    split_kernel<<<(KVD*DIM)/1024, 256>>>(Wk, wkh, wkl);
    split_kernel<<<(KVD*DIM)/1024, 256>>>(Wv, wvh, wvl);
    split_kernel<<<(DIM*DIM)/1024, 256>>>(Wo, woh, wol);

    k_gemm<<<dim3(DIM/128, TOK/128), 256, SMEM_BYTES>>>(xh, xl, wqh, wql, qp, 1024, 1024, DIM, DIM);
    k_gemm<<<dim3(KVD/128, TOK/128), 256, SMEM_BYTES>>>(xh, xl, wkh, wkl, kp, 1024, 1024, KVD, DIM);
    k_gemm<<<dim3(KVD/128, TOK/128), 256, SMEM_BYTES>>>(xh, xl, wvh, wvl, vp, 1024, 1024, KVD, DIM);

    qnorm_kernel<<<(NBH*SEQ*32)/256, 256>>>(gain);
    knorm_kernel<<<(BSZ*NKV*SEQ*32)/256, 256>>>();
    vtrans_kernel<<<dim3(SEQ/32, KVD/32, BSZ), dim3(32, 8)>>>();

    k_flash<<<dim3(SEQ/128, NBH), 256, FLASH_SMEM>>>();

    k_gemm<<<dim3(DIM/128, TOK/128), 256, SMEM_BYTES>>>(aoh, aol, woh, wol, out, 1024, 1024, DIM, DIM);
}